// round 11
// baseline (speedup 1.0000x reference)
#include <cuda_runtime.h>
#include <cuda_fp16.h>
#include <cuda_bf16.h>

typedef unsigned long long ull;

#define BB 8
#define TT 4
#define NN 4096
#define EE 65536
#define EF (EE + NN)          // edges + self loops = 69632
#define BN (BB * NN)          // 32768

// ---------------- device scratch ----------------
__device__ __half2 g_hgat2[NN * BB * 32];  // [(n*8+b)*32 + lane] = cols (2l, 2l+1)
__device__ float   g_est[NN * BB];         // es, transposed [n*8 + b]
__device__ float   g_edt[NN * BB];         // ed, transposed [n*8 + b]
__device__ float   g_s[BN * 64];           // GAT output, [b*NN+n][64]
__device__ float   g_h[BN * 64];           // GRU hidden state
__device__ int     g_cnt[NN];
__device__ int     g_cur[NN];
__device__ int     g_off[NN + 1];
__device__ int     g_srcs[EF];

// ---------------- f32x2 helpers ----------------
__device__ __forceinline__ ull pack2(float a, float b) {
    ull r; asm("mov.b64 %0, {%1, %2};" : "=l"(r) : "f"(a), "f"(b)); return r;
}
__device__ __forceinline__ ull d2(float v) {          // (v, v)
    ull r; asm("mov.b64 %0, {%1, %1};" : "=l"(r) : "f"(v)); return r;
}
__device__ __forceinline__ void unpack2(ull v, float& a, float& b) {
    asm("mov.b64 {%0, %1}, %2;" : "=f"(a), "=f"(b) : "l"(v));
}
__device__ __forceinline__ ull fma2(ull a, ull b, ull c) {
    ull d; asm("fma.rn.f32x2 %0, %1, %2, %3;" : "=l"(d) : "l"(a), "l"(b), "l"(c));
    return d;
}

// ---------------- kernel 1: edge count + GAT step-0 node transform ----------------
// h=0 at t=0, so hgat = x @ W[64:67]
__global__ __launch_bounds__(256) void gat0_count_kernel(
    const float* __restrict__ x, const float* __restrict__ gat_W,
    const float* __restrict__ a_src, const float* __restrict__ a_dst,
    const int* __restrict__ dst)
{
    if (blockIdx.x >= 4096) {
        int i = (blockIdx.x - 4096) * 256 + threadIdx.x;
        if (i < EF) {
            int d = (i < EE) ? dst[i] : (i - EE);
            atomicAdd(&g_cnt[d], 1);
        }
        return;
    }
    int w = threadIdx.x >> 5, lane = threadIdx.x & 31;
    int nid = blockIdx.x * 8 + w;
    int b = nid >> 12, n = nid & 4095;
    const float* xp = &x[((b * TT + 0) * NN + n) * 3];
    float x0 = __ldg(xp), x1 = __ldg(xp + 1), x2 = __ldg(xp + 2);
    int c0 = 2 * lane, c1 = 2 * lane + 1;
    float h0 = x0 * __ldg(&gat_W[64 * 64 + c0]) + x1 * __ldg(&gat_W[65 * 64 + c0])
             + x2 * __ldg(&gat_W[66 * 64 + c0]);
    float h1 = x0 * __ldg(&gat_W[64 * 64 + c1]) + x1 * __ldg(&gat_W[65 * 64 + c1])
             + x2 * __ldg(&gat_W[66 * 64 + c1]);
    g_hgat2[(n * 8 + b) * 32 + lane] = __floats2half2_rn(h0, h1);
    float es = h0 * __ldg(&a_src[c0]) + h1 * __ldg(&a_src[c1]);
    float ed = h0 * __ldg(&a_dst[c0]) + h1 * __ldg(&a_dst[c1]);
    #pragma unroll
    for (int o = 16; o > 0; o >>= 1) {
        es += __shfl_down_sync(0xFFFFFFFFu, es, o);
        ed += __shfl_down_sync(0xFFFFFFFFu, ed, o);
    }
    if (lane == 0) { g_est[n * 8 + b] = es; g_edt[n * 8 + b] = ed; }
}

// ---------------- kernel 2: prefix scan (+ re-zero counters for graph replay) ----
__global__ void scan_kernel() {
    __shared__ int tsum[1024];
    int tid = threadIdx.x;
    int base = tid * 4;
    int c0 = g_cnt[base + 0], c1 = g_cnt[base + 1];
    int c2 = g_cnt[base + 2], c3 = g_cnt[base + 3];
    int sum4 = c0 + c1 + c2 + c3;
    tsum[tid] = sum4;
    __syncthreads();
    for (int ofs = 1; ofs < 1024; ofs <<= 1) {
        int add = 0;
        if (tid >= ofs) add = tsum[tid - ofs];
        __syncthreads();
        tsum[tid] += add;
        __syncthreads();
    }
    int excl = tsum[tid] - sum4;
    g_off[base + 0] = excl;
    g_off[base + 1] = excl + c0;
    g_off[base + 2] = excl + c0 + c1;
    g_off[base + 3] = excl + c0 + c1 + c2;
    if (tid == 1023) g_off[NN] = tsum[1023];
    g_cnt[base + 0] = 0; g_cnt[base + 1] = 0; g_cnt[base + 2] = 0; g_cnt[base + 3] = 0;
    g_cur[base + 0] = 0; g_cur[base + 1] = 0; g_cur[base + 2] = 0; g_cur[base + 3] = 0;
}

// ---------------- kernel 3: CSR scatter ----------------
__global__ void scatter_kernel(const int* __restrict__ src, const int* __restrict__ dst) {
    int i = blockIdx.x * blockDim.x + threadIdx.x;
    if (i >= EF) return;
    int s, d;
    if (i < EE) { s = src[i]; d = dst[i]; }
    else        { s = i - EE; d = i - EE; }
    int pos = g_off[d] + atomicAdd(&g_cur[d], 1);
    g_srcs[pos] = s;
}

// ---------------- kernel 4: gather, 4 batches per warp ----------------
// warp group gw covers node n = gw>>1, batches (gw&1)*4 .. +3
__global__ __launch_bounds__(256) void gat_gather_kernel(const float* __restrict__ gat_b)
{
    int gw = blockIdx.x * 8 + (threadIdx.x >> 5);    // 0..8191
    int n = gw >> 1, bg = (gw & 1) * 4;
    int lane = threadIdx.x & 31;

    float4 ed4 = *(const float4*)&g_edt[n * 8 + bg];
    float edv[4] = {ed4.x, ed4.y, ed4.z, ed4.w};
    float S[4], a0[4], a1[4];
    #pragma unroll
    for (int b = 0; b < 4; b++) { S[b] = 0.0f; a0[b] = 0.0f; a1[b] = 0.0f; }

    int e = g_off[n], en = g_off[n + 1];
    for (; e < en; e++) {
        int s = __ldg(&g_srcs[e]);
        float4 es4 = *(const float4*)&g_est[s * 8 + bg];
        float esv[4] = {es4.x, es4.y, es4.z, es4.w};
        const __half2* hp = &g_hgat2[(s * 8 + bg) * 32 + lane];
        #pragma unroll
        for (int b = 0; b < 4; b++) {
            float ev = esv[b] + edv[b];
            ev = fmaxf(ev, 0.2f * ev);            // leaky_relu(0.2)
            float w = __expf(ev);
            float2 f = __half22float2(hp[b * 32]);
            S[b] += w; a0[b] += w * f.x; a1[b] += w * f.y;
        }
    }
    float gb0 = __ldg(&gat_b[2 * lane]), gb1 = __ldg(&gat_b[2 * lane + 1]);
    #pragma unroll
    for (int b = 0; b < 4; b++) {
        float inv = 1.0f / S[b];
        ((float2*)(g_s + ((bg + b) * NN + n) * 64))[lane] =
            make_float2(a0[b] * inv + gb0, a1[b] * inv + gb1);
    }
}

// ---------------- kernel 5: GAT node transform (steps 1..3) ----------------
// 256 threads, 64 nodes/block. 4-node x 4-col register tiles, FFMA2 inner loop.
__global__ __launch_bounds__(256) void gat_node_kernel(
    const float* __restrict__ x, const float* __restrict__ gat_W,
    const float* __restrict__ a_src, const float* __restrict__ a_dst, int t)
{
    __shared__ float sW[67 * 64];
    __shared__ float sz[64][68];
    __shared__ float sa[128];

    int tid = threadIdx.x;
    for (int i = tid; i < 1072; i += 256)
        ((float4*)sW)[i] = ((const float4*)gat_W)[i];
    if (tid < 128) sa[tid] = (tid < 64) ? a_src[tid] : a_dst[tid - 64];

    int nbase = blockIdx.x * 64;
    for (int i = tid; i < 1024; i += 256) {
        int ln = i >> 4, kq = i & 15;
        float4 v = ((const float4*)g_h)[(nbase + ln) * 16 + kq];
        sz[ln][kq * 4 + 0] = v.x; sz[ln][kq * 4 + 1] = v.y;
        sz[ln][kq * 4 + 2] = v.z; sz[ln][kq * 4 + 3] = v.w;
    }
    if (tid < 192) {
        int ln = tid / 3, f = tid % 3;
        int nid = nbase + ln;
        int b = nid >> 12, n = nid & 4095;
        sz[ln][64 + f] = x[((b * TT + t) * NN + n) * 3 + f];
    }
    __syncthreads();

    int j4 = (tid & 15) * 4;
    int g  = tid >> 4;
    ull acc01[4] = {0ull, 0ull, 0ull, 0ull};
    ull acc23[4] = {0ull, 0ull, 0ull, 0ull};

    #pragma unroll 4
    for (int k = 0; k < 67; k++) {
        ulonglong2 wv = *(const ulonglong2*)&sW[k * 64 + j4];
        #pragma unroll
        for (int i = 0; i < 4; i++) {
            ull z = d2(sz[g * 4 + i][k]);
            acc01[i] = fma2(z, wv.x, acc01[i]);
            acc23[i] = fma2(z, wv.y, acc23[i]);
        }
    }

    #pragma unroll
    for (int i = 0; i < 4; i++) {
        int nid = nbase + g * 4 + i;
        int b = nid >> 12, n = nid & 4095;
        float v0, v1c, v2c, v3;
        unpack2(acc01[i], v0, v1c);
        unpack2(acc23[i], v2c, v3);
        int p = j4 >> 1;
        g_hgat2[(n * 8 + b) * 32 + p]     = __floats2half2_rn(v0, v1c);
        g_hgat2[(n * 8 + b) * 32 + p + 1] = __floats2half2_rn(v2c, v3);

        float v1 = v0 * sa[j4]      + v1c * sa[j4 + 1]
                 + v2c * sa[j4 + 2] + v3  * sa[j4 + 3];
        float v2 = v0 * sa[64 + j4]      + v1c * sa[64 + j4 + 1]
                 + v2c * sa[64 + j4 + 2] + v3  * sa[64 + j4 + 3];
        #pragma unroll
        for (int o2 = 8; o2 > 0; o2 >>= 1) {
            v1 += __shfl_down_sync(0xFFFFFFFFu, v1, o2, 16);
            v2 += __shfl_down_sync(0xFFFFFFFFu, v2, o2, 16);
        }
        if ((tid & 15) == 0) { g_est[n * 8 + b] = v1; g_edt[n * 8 + b] = v2; }
    }
}

// ---------------- kernel 6: GRU cell (+ fused output projection on last step) ----
// 256 threads, 32 nodes/block, FFMA2 inner loops.
__global__ __launch_bounds__(256) void gru_kernel(
    const float* __restrict__ x,
    const float* __restrict__ W1, const float* __restrict__ b1,
    const float* __restrict__ W2, const float* __restrict__ b2,
    const float* __restrict__ oW, const float* __restrict__ ob,
    float* __restrict__ out, int t, int last)
{
    __shared__ float sW[67 * 128];    // 34.3 KB, phase2 reuses lower 67*64
    __shared__ float sz[32][68];      // [s (0..63), x (64..66)]
    __shared__ float sb1[128];
    __shared__ float sb2[64];
    __shared__ float sow[192];
    __shared__ float sob[4];
    float* srs = sW + 67 * 64;                 // r*s, aliases dead upper W1
    float* su  = sW + 67 * 64 + 32 * 64;       // u

    int tid = threadIdx.x;
    int nbase = blockIdx.x * 32;

    for (int i = tid; i < 2144; i += 256)
        ((float4*)sW)[i] = ((const float4*)W1)[i];
    if (tid < 128) sb1[tid] = b1[tid];
    if (tid < 64)  sb2[tid] = b2[tid];
    if (last) {
        if (tid < 192) sow[tid] = oW[tid];
        if (tid < 3)   sob[tid] = ob[tid];
    }

    for (int i = tid; i < 512; i += 256) {
        int ln = i >> 4, kq = (i & 15) * 4;
        float4 v = ((const float4*)g_s)[(nbase + ln) * 16 + (i & 15)];
        sz[ln][kq + 0] = v.x; sz[ln][kq + 1] = v.y;
        sz[ln][kq + 2] = v.z; sz[ln][kq + 3] = v.w;
    }
    if (tid < 96) {
        int ln = tid / 3, f = tid % 3;
        int nid = nbase + ln;
        int b = nid >> 12, n = nid & 4095;
        sz[ln][64 + f] = x[((b * TT + t) * NN + n) * 3 + f];
    }
    __syncthreads();

    // ---- phase 1: ru = sigmoid([x, s] @ W1 + b1) ----  (W1 rows: 0..2 x, 3..66 s)
    int j4 = (tid & 31) * 4;
    int g  = tid >> 5;
    ull acc01[4], acc23[4];
    {
        ull i01 = pack2(sb1[j4], sb1[j4 + 1]);
        ull i23 = pack2(sb1[j4 + 2], sb1[j4 + 3]);
        #pragma unroll
        for (int i = 0; i < 4; i++) { acc01[i] = i01; acc23[i] = i23; }
    }
    #pragma unroll
    for (int f = 0; f < 3; f++) {
        ulonglong2 wv = *(const ulonglong2*)&sW[f * 128 + j4];
        #pragma unroll
        for (int i = 0; i < 4; i++) {
            ull z = d2(sz[g * 4 + i][64 + f]);
            acc01[i] = fma2(z, wv.x, acc01[i]);
            acc23[i] = fma2(z, wv.y, acc23[i]);
        }
    }
    #pragma unroll 4
    for (int k = 0; k < 64; k++) {
        ulonglong2 wv = *(const ulonglong2*)&sW[(3 + k) * 128 + j4];
        #pragma unroll
        for (int i = 0; i < 4; i++) {
            ull z = d2(sz[g * 4 + i][k]);
            acc01[i] = fma2(z, wv.x, acc01[i]);
            acc23[i] = fma2(z, wv.y, acc23[i]);
        }
    }
    __syncthreads();   // all W1 reads done before aliasing upper half

    #pragma unroll
    for (int i = 0; i < 4; i++) {
        int n = g * 4 + i;
        float v[4];
        unpack2(acc01[i], v[0], v[1]);
        unpack2(acc23[i], v[2], v[3]);
        #pragma unroll
        for (int c = 0; c < 4; c++) {
            float sg = 1.0f / (1.0f + __expf(-v[c]));
            if (j4 < 64) srs[n * 64 + j4 + c] = sg * sz[n][j4 + c];
            else         su[n * 64 + (j4 - 64) + c] = sg;
        }
    }
    for (int i = tid; i < 1072; i += 256)
        ((float4*)sW)[i] = ((const float4*)W2)[i];
    __syncthreads();

    // ---- phase 2: c = tanh([x, r*s] @ W2 + b2); h = u*s + (1-u)*c ----
    int j4b = (tid & 15) * 4;
    int g2  = tid >> 4;
    ull a01[2], a23[2];
    {
        ull i01 = pack2(sb2[j4b], sb2[j4b + 1]);
        ull i23 = pack2(sb2[j4b + 2], sb2[j4b + 3]);
        a01[0] = i01; a01[1] = i01; a23[0] = i23; a23[1] = i23;
    }
    #pragma unroll
    for (int f = 0; f < 3; f++) {
        ulonglong2 wv = *(const ulonglong2*)&sW[f * 64 + j4b];
        #pragma unroll
        for (int i = 0; i < 2; i++) {
            ull z = d2(sz[g2 * 2 + i][64 + f]);
            a01[i] = fma2(z, wv.x, a01[i]);
            a23[i] = fma2(z, wv.y, a23[i]);
        }
    }
    #pragma unroll 4
    for (int k = 0; k < 64; k++) {
        ulonglong2 wv = *(const ulonglong2*)&sW[(3 + k) * 64 + j4b];
        #pragma unroll
        for (int i = 0; i < 2; i++) {
            ull z = d2(srs[(g2 * 2 + i) * 64 + k]);
            a01[i] = fma2(z, wv.x, a01[i]);
            a23[i] = fma2(z, wv.y, a23[i]);
        }
    }

    float hh[2][4];
    #pragma unroll
    for (int i = 0; i < 2; i++) {
        int n = g2 * 2 + i;
        float v[4];
        unpack2(a01[i], v[0], v[1]);
        unpack2(a23[i], v[2], v[3]);
        #pragma unroll
        for (int c = 0; c < 4; c++) {
            float cc = tanhf(v[c]);
            float u = su[n * 64 + j4b + c];
            float s = sz[n][j4b + c];
            hh[i][c] = u * s + (1.0f - u) * cc;
        }
    }

    if (!last) {
        #pragma unroll
        for (int i = 0; i < 2; i++) {
            int nid = nbase + g2 * 2 + i;
            ((float4*)g_h)[nid * 16 + (j4b >> 2)] =
                make_float4(hh[i][0], hh[i][1], hh[i][2], hh[i][3]);
        }
    } else {
        __syncthreads();   // all reads of sz(s) done before overwrite with h
        #pragma unroll
        for (int i = 0; i < 2; i++)
            #pragma unroll
            for (int c = 0; c < 4; c++) sz[g2 * 2 + i][j4b + c] = hh[i][c];
        __syncthreads();
        if (tid < 96) {
            int ln = tid / 3, d = tid % 3;
            float acc3 = sob[d];
            #pragma unroll 8
            for (int k = 0; k < 64; k++) acc3 += sz[ln][k] * sow[k * 3 + d];
            out[(nbase + ln) * 3 + d] = acc3;
        }
    }
}

// ---------------- launch ----------------
extern "C" void kernel_launch(void* const* d_in, const int* in_sizes, int n_in,
                              void* d_out, int out_size)
{
    const float* x       = (const float*)d_in[0];
    const int*   src     = (const int*)  d_in[1];
    const int*   dst     = (const int*)  d_in[2];
    const float* gat_W   = (const float*)d_in[3];
    const float* a_src   = (const float*)d_in[4];
    const float* a_dst   = (const float*)d_in[5];
    const float* gat_b   = (const float*)d_in[6];
    const float* gru1_W  = (const float*)d_in[7];
    const float* gru1_b  = (const float*)d_in[8];
    const float* gru2_W  = (const float*)d_in[9];
    const float* gru2_b  = (const float*)d_in[10];
    const float* out_W   = (const float*)d_in[11];
    const float* out_b   = (const float*)d_in[12];
    float* out = (float*)d_out;

    gat0_count_kernel<<<4096 + 272, 256>>>(x, gat_W, a_src, a_dst, dst);
    scan_kernel<<<1, 1024>>>();
    scatter_kernel<<<(EF + 255) / 256, 256>>>(src, dst);

    for (int t = 0; t < TT; t++) {
        gat_gather_kernel<<<NN / 4, 256>>>(gat_b);
        gru_kernel<<<BN / 32, 256>>>(x, gru1_W, gru1_b, gru2_W, gru2_b,
                                     out_W, out_b, out, t, (t == TT - 1) ? 1 : 0);
        if (t < TT - 1)
            gat_node_kernel<<<BN / 64, 256>>>(x, gat_W, a_src, a_dst, t + 1);
    }
}

// round 12
// speedup vs baseline: 1.0168x; 1.0168x over previous
#include <cuda_runtime.h>
#include <cuda_fp16.h>
#include <cuda_bf16.h>

#define BB 8
#define TT 4
#define NN 4096
#define EE 65536
#define EF (EE + NN)          // edges + self loops = 69632
#define BN (BB * NN)          // 32768

// ---------------- device scratch ----------------
// hgat in fp16, layout [n][colpair p (32)][batch b (8)] as half2; uint4 = 4 batches
__device__ uint4   g_hgat4[NN * 32 * 2];   // 4 MB
__device__ float   g_est[NN * BB];         // es, transposed [n*8 + b]
__device__ float   g_edt[NN * BB];         // ed, transposed [n*8 + b]
__device__ float   g_s[BN * 64];           // GAT output, [b*NN+n][64]
__device__ float   g_h[BN * 64];           // GRU hidden state
__device__ int     g_cnt[NN];
__device__ int     g_cur[NN];
__device__ int     g_off[NN + 1];
__device__ int     g_srcs[EF];

// ---------------- kernel 1: edge count + GAT step-0 node transform ----------------
// h=0 at t=0, so hgat = x @ W[64:67]
__global__ __launch_bounds__(256) void gat0_count_kernel(
    const float* __restrict__ x, const float* __restrict__ gat_W,
    const float* __restrict__ a_src, const float* __restrict__ a_dst,
    const int* __restrict__ dst)
{
    if (blockIdx.x >= 4096) {
        int i = (blockIdx.x - 4096) * 256 + threadIdx.x;
        if (i < EF) {
            int d = (i < EE) ? dst[i] : (i - EE);
            atomicAdd(&g_cnt[d], 1);
        }
        return;
    }
    int w = threadIdx.x >> 5, lane = threadIdx.x & 31;
    int nid = blockIdx.x * 8 + w;
    int b = nid >> 12, n = nid & 4095;
    const float* xp = &x[((b * TT + 0) * NN + n) * 3];
    float x0 = __ldg(xp), x1 = __ldg(xp + 1), x2 = __ldg(xp + 2);
    int c0 = 2 * lane, c1 = 2 * lane + 1;
    float h0 = x0 * __ldg(&gat_W[64 * 64 + c0]) + x1 * __ldg(&gat_W[65 * 64 + c0])
             + x2 * __ldg(&gat_W[66 * 64 + c0]);
    float h1 = x0 * __ldg(&gat_W[64 * 64 + c1]) + x1 * __ldg(&gat_W[65 * 64 + c1])
             + x2 * __ldg(&gat_W[66 * 64 + c1]);
    ((__half2*)g_hgat4)[(n * 32 + lane) * 8 + b] = __floats2half2_rn(h0, h1);
    float es = h0 * __ldg(&a_src[c0]) + h1 * __ldg(&a_src[c1]);
    float ed = h0 * __ldg(&a_dst[c0]) + h1 * __ldg(&a_dst[c1]);
    #pragma unroll
    for (int o = 16; o > 0; o >>= 1) {
        es += __shfl_down_sync(0xFFFFFFFFu, es, o);
        ed += __shfl_down_sync(0xFFFFFFFFu, ed, o);
    }
    if (lane == 0) { g_est[n * 8 + b] = es; g_edt[n * 8 + b] = ed; }
}

// ---------------- kernel 2: prefix scan (+ re-zero counters for graph replay) ----
__global__ void scan_kernel() {
    __shared__ int tsum[1024];
    int tid = threadIdx.x;
    int base = tid * 4;
    int c0 = g_cnt[base + 0], c1 = g_cnt[base + 1];
    int c2 = g_cnt[base + 2], c3 = g_cnt[base + 3];
    int sum4 = c0 + c1 + c2 + c3;
    tsum[tid] = sum4;
    __syncthreads();
    for (int ofs = 1; ofs < 1024; ofs <<= 1) {
        int add = 0;
        if (tid >= ofs) add = tsum[tid - ofs];
        __syncthreads();
        tsum[tid] += add;
        __syncthreads();
    }
    int excl = tsum[tid] - sum4;
    g_off[base + 0] = excl;
    g_off[base + 1] = excl + c0;
    g_off[base + 2] = excl + c0 + c1;
    g_off[base + 3] = excl + c0 + c1 + c2;
    if (tid == 1023) g_off[NN] = tsum[1023];
    g_cnt[base + 0] = 0; g_cnt[base + 1] = 0; g_cnt[base + 2] = 0; g_cnt[base + 3] = 0;
    g_cur[base + 0] = 0; g_cur[base + 1] = 0; g_cur[base + 2] = 0; g_cur[base + 3] = 0;
}

// ---------------- kernel 3: CSR scatter ----------------
__global__ void scatter_kernel(const int* __restrict__ src, const int* __restrict__ dst) {
    int i = blockIdx.x * blockDim.x + threadIdx.x;
    if (i >= EF) return;
    int s, d;
    if (i < EE) { s = src[i]; d = dst[i]; }
    else        { s = i - EE; d = i - EE; }
    int pos = g_off[d] + atomicAdd(&g_cur[d], 1);
    g_srcs[pos] = s;
}

// ---------------- kernel 4: gather, 4 batches per warp, pipelined ----------------
// warp group gw: node n = gw>>1, batches bg = (gw&1)*4 .. +3
// per edge: 1x LDG srcs + 1x LDG.128 est + 1x LDG.128 hgat (vs 6 loads before)
__global__ __launch_bounds__(256) void gat_gather_kernel(const float* __restrict__ gat_b)
{
    int gw = blockIdx.x * 8 + (threadIdx.x >> 5);    // 0..8191
    int n = gw >> 1, bg = (gw & 1) * 4, bq = gw & 1;
    int lane = threadIdx.x & 31;

    float4 ed4 = *(const float4*)&g_edt[n * 8 + bg];
    float edv[4] = {ed4.x, ed4.y, ed4.z, ed4.w};
    float S[4], a0[4], a1[4];
    #pragma unroll
    for (int b = 0; b < 4; b++) { S[b] = 0.0f; a0[b] = 0.0f; a1[b] = 0.0f; }

    int e = g_off[n], en = g_off[n + 1];
    // prologue: issue loads for first edge (degree >= 1 due to self-loop)
    int s0 = __ldg(&g_srcs[e]);
    float4 es4 = *(const float4*)&g_est[s0 * 8 + bg];
    uint4  h4  = __ldg(&g_hgat4[(s0 * 32 + lane) * 2 + bq]);

    for (;;) {
        float4 ces = es4;
        uint4  ch  = h4;
        e++;
        bool more = (e < en);
        if (more) {   // issue next edge's loads before consuming current
            int s1 = __ldg(&g_srcs[e]);
            es4 = *(const float4*)&g_est[s1 * 8 + bg];
            h4  = __ldg(&g_hgat4[(s1 * 32 + lane) * 2 + bq]);
        }
        float esv[4] = {ces.x, ces.y, ces.z, ces.w};
        unsigned hw[4] = {ch.x, ch.y, ch.z, ch.w};
        #pragma unroll
        for (int b = 0; b < 4; b++) {
            float ev = esv[b] + edv[b];
            ev = fmaxf(ev, 0.2f * ev);            // leaky_relu(0.2)
            float w = __expf(ev);
            float2 f = __half22float2(*(__half2*)&hw[b]);
            S[b] += w; a0[b] += w * f.x; a1[b] += w * f.y;
        }
        if (!more) break;
    }
    float gb0 = __ldg(&gat_b[2 * lane]), gb1 = __ldg(&gat_b[2 * lane + 1]);
    #pragma unroll
    for (int b = 0; b < 4; b++) {
        float inv = 1.0f / S[b];
        ((float2*)(g_s + ((bg + b) * NN + n) * 64))[lane] =
            make_float2(a0[b] * inv + gb0, a1[b] * inv + gb1);
    }
}

// ---------------- kernel 5: GAT node transform (steps 1..3) ----------------
// 256 threads, 64 nodes/block. 4-node x 4-col register tiles (round-10 proven).
__global__ __launch_bounds__(256) void gat_node_kernel(
    const float* __restrict__ x, const float* __restrict__ gat_W,
    const float* __restrict__ a_src, const float* __restrict__ a_dst, int t)
{
    __shared__ float sW[67 * 64];
    __shared__ float sz[64][68];
    __shared__ float sa[128];

    int tid = threadIdx.x;
    for (int i = tid; i < 1072; i += 256)
        ((float4*)sW)[i] = ((const float4*)gat_W)[i];
    if (tid < 128) sa[tid] = (tid < 64) ? a_src[tid] : a_dst[tid - 64];

    int nbase = blockIdx.x * 64;
    for (int i = tid; i < 1024; i += 256) {
        int ln = i >> 4, kq = i & 15;
        float4 v = ((const float4*)g_h)[(nbase + ln) * 16 + kq];
        sz[ln][kq * 4 + 0] = v.x; sz[ln][kq * 4 + 1] = v.y;
        sz[ln][kq * 4 + 2] = v.z; sz[ln][kq * 4 + 3] = v.w;
    }
    if (tid < 192) {
        int ln = tid / 3, f = tid % 3;
        int nid = nbase + ln;
        int b = nid >> 12, n = nid & 4095;
        sz[ln][64 + f] = x[((b * TT + t) * NN + n) * 3 + f];
    }
    __syncthreads();

    int j4 = (tid & 15) * 4;
    int g  = tid >> 4;
    float acc[4][4];
    #pragma unroll
    for (int i = 0; i < 4; i++)
        #pragma unroll
        for (int c = 0; c < 4; c++) acc[i][c] = 0.0f;

    #pragma unroll 4
    for (int k = 0; k < 67; k++) {
        float4 w = *(float4*)&sW[k * 64 + j4];
        #pragma unroll
        for (int i = 0; i < 4; i++) {
            float z = sz[g * 4 + i][k];
            acc[i][0] += z * w.x; acc[i][1] += z * w.y;
            acc[i][2] += z * w.z; acc[i][3] += z * w.w;
        }
    }

    #pragma unroll
    for (int i = 0; i < 4; i++) {
        int nid = nbase + g * 4 + i;
        int b = nid >> 12, n = nid & 4095;
        int p = j4 >> 1;
        ((__half2*)g_hgat4)[(n * 32 + p) * 8 + b]     = __floats2half2_rn(acc[i][0], acc[i][1]);
        ((__half2*)g_hgat4)[(n * 32 + p + 1) * 8 + b] = __floats2half2_rn(acc[i][2], acc[i][3]);

        float v1 = acc[i][0] * sa[j4]      + acc[i][1] * sa[j4 + 1]
                 + acc[i][2] * sa[j4 + 2]  + acc[i][3] * sa[j4 + 3];
        float v2 = acc[i][0] * sa[64 + j4]     + acc[i][1] * sa[64 + j4 + 1]
                 + acc[i][2] * sa[64 + j4 + 2] + acc[i][3] * sa[64 + j4 + 3];
        #pragma unroll
        for (int o2 = 8; o2 > 0; o2 >>= 1) {
            v1 += __shfl_down_sync(0xFFFFFFFFu, v1, o2, 16);
            v2 += __shfl_down_sync(0xFFFFFFFFu, v2, o2, 16);
        }
        if ((tid & 15) == 0) { g_est[n * 8 + b] = v1; g_edt[n * 8 + b] = v2; }
    }
}

// ---------------- kernel 6: GRU cell (+ fused output projection on last step) ----
// 256 threads, 32 nodes/block (round-10 proven float4 version).
__global__ __launch_bounds__(256) void gru_kernel(
    const float* __restrict__ x,
    const float* __restrict__ W1, const float* __restrict__ b1,
    const float* __restrict__ W2, const float* __restrict__ b2,
    const float* __restrict__ oW, const float* __restrict__ ob,
    float* __restrict__ out, int t, int last)
{
    __shared__ float sW[67 * 128];    // 34.3 KB, phase2 reuses lower 67*64
    __shared__ float sz[32][68];      // [s (0..63), x (64..66)]
    __shared__ float sb1[128];
    __shared__ float sb2[64];
    __shared__ float sow[192];
    __shared__ float sob[4];
    float* srs = sW + 67 * 64;                 // r*s, aliases dead upper W1
    float* su  = sW + 67 * 64 + 32 * 64;       // u

    int tid = threadIdx.x;
    int nbase = blockIdx.x * 32;

    for (int i = tid; i < 2144; i += 256)
        ((float4*)sW)[i] = ((const float4*)W1)[i];
    if (tid < 128) sb1[tid] = b1[tid];
    if (tid < 64)  sb2[tid] = b2[tid];
    if (last) {
        if (tid < 192) sow[tid] = oW[tid];
        if (tid < 3)   sob[tid] = ob[tid];
    }

    for (int i = tid; i < 512; i += 256) {
        int ln = i >> 4, kq = (i & 15) * 4;
        float4 v = ((const float4*)g_s)[(nbase + ln) * 16 + (i & 15)];
        sz[ln][kq + 0] = v.x; sz[ln][kq + 1] = v.y;
        sz[ln][kq + 2] = v.z; sz[ln][kq + 3] = v.w;
    }
    if (tid < 96) {
        int ln = tid / 3, f = tid % 3;
        int nid = nbase + ln;
        int b = nid >> 12, n = nid & 4095;
        sz[ln][64 + f] = x[((b * TT + t) * NN + n) * 3 + f];
    }
    __syncthreads();

    // ---- phase 1: ru = sigmoid([x, s] @ W1 + b1) ----  (W1 rows: 0..2 x, 3..66 s)
    int j4 = (tid & 31) * 4;
    int g  = tid >> 5;
    float acc[4][4];
    #pragma unroll
    for (int i = 0; i < 4; i++)
        #pragma unroll
        for (int c = 0; c < 4; c++) acc[i][c] = sb1[j4 + c];

    #pragma unroll
    for (int f = 0; f < 3; f++) {
        float4 wv = *(float4*)&sW[f * 128 + j4];
        #pragma unroll
        for (int i = 0; i < 4; i++) {
            float z = sz[g * 4 + i][64 + f];
            acc[i][0] += z * wv.x; acc[i][1] += z * wv.y;
            acc[i][2] += z * wv.z; acc[i][3] += z * wv.w;
        }
    }
    #pragma unroll 4
    for (int k = 0; k < 64; k++) {
        float4 wv = *(float4*)&sW[(3 + k) * 128 + j4];
        #pragma unroll
        for (int i = 0; i < 4; i++) {
            float z = sz[g * 4 + i][k];
            acc[i][0] += z * wv.x; acc[i][1] += z * wv.y;
            acc[i][2] += z * wv.z; acc[i][3] += z * wv.w;
        }
    }
    __syncthreads();

    #pragma unroll
    for (int i = 0; i < 4; i++) {
        int n = g * 4 + i;
        #pragma unroll
        for (int c = 0; c < 4; c++) {
            float v = 1.0f / (1.0f + __expf(-acc[i][c]));
            if (j4 < 64) srs[n * 64 + j4 + c] = v * sz[n][j4 + c];
            else         su[n * 64 + (j4 - 64) + c] = v;
        }
    }
    for (int i = tid; i < 1072; i += 256)
        ((float4*)sW)[i] = ((const float4*)W2)[i];
    __syncthreads();

    // ---- phase 2: c = tanh([x, r*s] @ W2 + b2); h = u*s + (1-u)*c ----
    int j4b = (tid & 15) * 4;
    int g2  = tid >> 4;
    float a2[2][4];
    #pragma unroll
    for (int i = 0; i < 2; i++)
        #pragma unroll
        for (int c = 0; c < 4; c++) a2[i][c] = sb2[j4b + c];

    #pragma unroll
    for (int f = 0; f < 3; f++) {
        float4 wv = *(float4*)&sW[f * 64 + j4b];
        #pragma unroll
        for (int i = 0; i < 2; i++) {
            float z = sz[g2 * 2 + i][64 + f];
            a2[i][0] += z * wv.x; a2[i][1] += z * wv.y;
            a2[i][2] += z * wv.z; a2[i][3] += z * wv.w;
        }
    }
    #pragma unroll 4
    for (int k = 0; k < 64; k++) {
        float4 wv = *(float4*)&sW[(3 + k) * 64 + j4b];
        #pragma unroll
        for (int i = 0; i < 2; i++) {
            float z = srs[(g2 * 2 + i) * 64 + k];
            a2[i][0] += z * wv.x; a2[i][1] += z * wv.y;
            a2[i][2] += z * wv.z; a2[i][3] += z * wv.w;
        }
    }

    float hh[2][4];
    #pragma unroll
    for (int i = 0; i < 2; i++) {
        int n = g2 * 2 + i;
        #pragma unroll
        for (int c = 0; c < 4; c++) {
            float cc = tanhf(a2[i][c]);
            float u = su[n * 64 + j4b + c];
            float s = sz[n][j4b + c];
            hh[i][c] = u * s + (1.0f - u) * cc;
        }
    }

    if (!last) {
        #pragma unroll
        for (int i = 0; i < 2; i++) {
            int nid = nbase + g2 * 2 + i;
            ((float4*)g_h)[nid * 16 + (j4b >> 2)] =
                make_float4(hh[i][0], hh[i][1], hh[i][2], hh[i][3]);
        }
    } else {
        __syncthreads();   // all reads of sz(s) done before overwrite with h
        #pragma unroll
        for (int i = 0; i < 2; i++)
            #pragma unroll
            for (int c = 0; c < 4; c++) sz[g2 * 2 + i][j4b + c] = hh[i][c];
        __syncthreads();
        if (tid < 96) {
            int ln = tid / 3, d = tid % 3;
            float acc3 = sob[d];
            #pragma unroll 8
            for (int k = 0; k < 64; k++) acc3 += sz[ln][k] * sow[k * 3 + d];
            out[(nbase + ln) * 3 + d] = acc3;
        }
    }
}

// ---------------- launch ----------------
extern "C" void kernel_launch(void* const* d_in, const int* in_sizes, int n_in,
                              void* d_out, int out_size)
{
    const float* x       = (const float*)d_in[0];
    const int*   src     = (const int*)  d_in[1];
    const int*   dst     = (const int*)  d_in[2];
    const float* gat_W   = (const float*)d_in[3];
    const float* a_src   = (const float*)d_in[4];
    const float* a_dst   = (const float*)d_in[5];
    const float* gat_b   = (const float*)d_in[6];
    const float* gru1_W  = (const float*)d_in[7];
    const float* gru1_b  = (const float*)d_in[8];
    const float* gru2_W  = (const float*)d_in[9];
    const float* gru2_b  = (const float*)d_in[10];
    const float* out_W   = (const float*)d_in[11];
    const float* out_b   = (const float*)d_in[12];
    float* out = (float*)d_out;

    gat0_count_kernel<<<4096 + 272, 256>>>(x, gat_W, a_src, a_dst, dst);
    scan_kernel<<<1, 1024>>>();
    scatter_kernel<<<(EF + 255) / 256, 256>>>(src, dst);

    for (int t = 0; t < TT; t++) {
        gat_gather_kernel<<<NN / 4, 256>>>(gat_b);
        gru_kernel<<<BN / 32, 256>>>(x, gru1_W, gru1_b, gru2_W, gru2_b,
                                     out_W, out_b, out, t, (t == TT - 1) ? 1 : 0);
        if (t < TT - 1)
            gat_node_kernel<<<BN / 64, 256>>>(x, gat_W, a_src, a_dst, t + 1);
    }
}

// round 13
// speedup vs baseline: 1.0522x; 1.0349x over previous
#include <cuda_runtime.h>
#include <cuda_fp16.h>
#include <cuda_bf16.h>

#define BB 8
#define TT 4
#define NN 4096
#define EE 65536
#define EF (EE + NN)          // edges + self loops = 69632
#define BN (BB * NN)          // 32768
#define LOG2E 1.44269504f

// ---------------- device scratch ----------------
// hgat in fp16, layout [n][colpair p (32)][batch b (8)] as half2; uint4 = 4 batches
__device__ uint4   g_hgat4[NN * 32 * 2];   // 4 MB
__device__ float   g_est[NN * BB];         // es * log2e, transposed [n*8 + b]
__device__ float   g_edt[NN * BB];         // ed * log2e, transposed [n*8 + b]
__device__ float   g_s[BN * 64];           // GAT output, [b*NN+n][64]
__device__ float   g_h[BN * 64];           // GRU hidden state
__device__ int     g_cnt[NN];
__device__ int     g_cur[NN];
__device__ int     g_off[NN + 1];
__device__ int     g_srcs[EF];

__device__ __forceinline__ float ex2(float x) {
    float r; asm("ex2.approx.f32 %0, %1;" : "=f"(r) : "f"(x)); return r;
}

// ---------------- kernel 1: edge count + GAT step-0 node transform ----------------
// h=0 at t=0, so hgat = x @ W[64:67]
__global__ __launch_bounds__(256) void gat0_count_kernel(
    const float* __restrict__ x, const float* __restrict__ gat_W,
    const float* __restrict__ a_src, const float* __restrict__ a_dst,
    const int* __restrict__ dst)
{
    if (blockIdx.x >= 4096) {
        int i = (blockIdx.x - 4096) * 256 + threadIdx.x;
        if (i < EF) {
            int d = (i < EE) ? dst[i] : (i - EE);
            atomicAdd(&g_cnt[d], 1);
        }
        return;
    }
    int w = threadIdx.x >> 5, lane = threadIdx.x & 31;
    int nid = blockIdx.x * 8 + w;
    int b = nid >> 12, n = nid & 4095;
    const float* xp = &x[((b * TT + 0) * NN + n) * 3];
    float x0 = __ldg(xp), x1 = __ldg(xp + 1), x2 = __ldg(xp + 2);
    int c0 = 2 * lane, c1 = 2 * lane + 1;
    float h0 = x0 * __ldg(&gat_W[64 * 64 + c0]) + x1 * __ldg(&gat_W[65 * 64 + c0])
             + x2 * __ldg(&gat_W[66 * 64 + c0]);
    float h1 = x0 * __ldg(&gat_W[64 * 64 + c1]) + x1 * __ldg(&gat_W[65 * 64 + c1])
             + x2 * __ldg(&gat_W[66 * 64 + c1]);
    ((__half2*)g_hgat4)[(n * 32 + lane) * 8 + b] = __floats2half2_rn(h0, h1);
    float es = h0 * __ldg(&a_src[c0]) + h1 * __ldg(&a_src[c1]);
    float ed = h0 * __ldg(&a_dst[c0]) + h1 * __ldg(&a_dst[c1]);
    #pragma unroll
    for (int o = 16; o > 0; o >>= 1) {
        es += __shfl_down_sync(0xFFFFFFFFu, es, o);
        ed += __shfl_down_sync(0xFFFFFFFFu, ed, o);
    }
    if (lane == 0) { g_est[n * 8 + b] = es * LOG2E; g_edt[n * 8 + b] = ed * LOG2E; }
}

// ---------------- kernel 2: prefix scan (+ re-zero counters for graph replay) ----
__global__ void scan_kernel() {
    __shared__ int tsum[1024];
    int tid = threadIdx.x;
    int base = tid * 4;
    int c0 = g_cnt[base + 0], c1 = g_cnt[base + 1];
    int c2 = g_cnt[base + 2], c3 = g_cnt[base + 3];
    int sum4 = c0 + c1 + c2 + c3;
    tsum[tid] = sum4;
    __syncthreads();
    for (int ofs = 1; ofs < 1024; ofs <<= 1) {
        int add = 0;
        if (tid >= ofs) add = tsum[tid - ofs];
        __syncthreads();
        tsum[tid] += add;
        __syncthreads();
    }
    int excl = tsum[tid] - sum4;
    g_off[base + 0] = excl;
    g_off[base + 1] = excl + c0;
    g_off[base + 2] = excl + c0 + c1;
    g_off[base + 3] = excl + c0 + c1 + c2;
    if (tid == 1023) g_off[NN] = tsum[1023];
    g_cnt[base + 0] = 0; g_cnt[base + 1] = 0; g_cnt[base + 2] = 0; g_cnt[base + 3] = 0;
    g_cur[base + 0] = 0; g_cur[base + 1] = 0; g_cur[base + 2] = 0; g_cur[base + 3] = 0;
}

// ---------------- kernel 3: CSR scatter ----------------
__global__ void scatter_kernel(const int* __restrict__ src, const int* __restrict__ dst) {
    int i = blockIdx.x * blockDim.x + threadIdx.x;
    if (i >= EF) return;
    int s, d;
    if (i < EE) { s = src[i]; d = dst[i]; }
    else        { s = i - EE; d = i - EE; }
    int pos = g_off[d] + atomicAdd(&g_cur[d], 1);
    g_srcs[pos] = s;
}

// ---------------- kernel 4: gather, 4 batches/warp, depth-2 pipeline -------------
// warp group gw: node n = gw>>1, batches bg = (gw&1)*4 .. +3
// srcs queue 2-ahead (sC resident, sD in flight); data slots 2 deep.
__global__ __launch_bounds__(256) void gat_gather_kernel(const float* __restrict__ gat_b)
{
    int gw = blockIdx.x * 8 + (threadIdx.x >> 5);    // 0..8191
    int n = gw >> 1, bg = (gw & 1) * 4, bq = gw & 1;
    int lane = threadIdx.x & 31;

    float4 ed4 = *(const float4*)&g_edt[n * 8 + bg];
    float edv[4] = {ed4.x, ed4.y, ed4.z, ed4.w};
    float S[4], a0[4], a1[4];
    #pragma unroll
    for (int b = 0; b < 4; b++) { S[b] = 0.0f; a0[b] = 0.0f; a1[b] = 0.0f; }

    int e0 = g_off[n];
    int en1 = g_off[n + 1] - 1;           // last valid edge index (deg >= 1)
    int cnt = en1 - e0 + 1;
    int hofs = lane * 2 + bq;

    // prologue: slots 0,1 <- edges 0,1 ; srcs queue holds edges 2,3
    int sA = __ldg(&g_srcs[e0]);
    int s1 = __ldg(&g_srcs[min(e0 + 1, en1)]);
    int sC = __ldg(&g_srcs[min(e0 + 2, en1)]);
    int sD = __ldg(&g_srcs[min(e0 + 3, en1)]);
    float4 esv[2]; uint4 hv[2];
    esv[0] = *(const float4*)&g_est[sA * 8 + bg];
    hv[0]  = __ldg(&g_hgat4[sA * 64 + hofs]);
    esv[1] = *(const float4*)&g_est[s1 * 8 + bg];
    hv[1]  = __ldg(&g_hgat4[s1 * 64 + hofs]);

    for (int i = 0; i < cnt; i++) {
        int cur = i & 1;
        float4 ces = esv[cur];
        uint4  ch  = hv[cur];
        // prefetch data for edge i+2 into slot cur (clamped; discarded at tail)
        esv[cur] = *(const float4*)&g_est[sC * 8 + bg];
        hv[cur]  = __ldg(&g_hgat4[sC * 64 + hofs]);
        sC = sD;
        sD = __ldg(&g_srcs[min(e0 + i + 4, en1)]);

        float esvv[4] = {ces.x, ces.y, ces.z, ces.w};
        unsigned hw[4] = {ch.x, ch.y, ch.z, ch.w};
        #pragma unroll
        for (int b = 0; b < 4; b++) {
            float ev = esvv[b] + edv[b];          // already * log2e
            ev = fmaxf(ev, 0.2f * ev);            // leaky_relu(0.2)
            float w = ex2(ev);                    // exp(leaky(es+ed))
            float2 f = __half22float2(*(__half2*)&hw[b]);
            S[b] += w; a0[b] += w * f.x; a1[b] += w * f.y;
        }
    }
    float gb0 = __ldg(&gat_b[2 * lane]), gb1 = __ldg(&gat_b[2 * lane + 1]);
    #pragma unroll
    for (int b = 0; b < 4; b++) {
        float inv = 1.0f / S[b];
        ((float2*)(g_s + ((bg + b) * NN + n) * 64))[lane] =
            make_float2(a0[b] * inv + gb0, a1[b] * inv + gb1);
    }
}

// ---------------- kernel 5: GAT node transform (steps 1..3) ----------------
// 256 threads, 64 nodes/block. 4-node x 4-col register tiles (round-10 proven).
__global__ __launch_bounds__(256) void gat_node_kernel(
    const float* __restrict__ x, const float* __restrict__ gat_W,
    const float* __restrict__ a_src, const float* __restrict__ a_dst, int t)
{
    __shared__ float sW[67 * 64];
    __shared__ float sz[64][68];
    __shared__ float sa[128];

    int tid = threadIdx.x;
    for (int i = tid; i < 1072; i += 256)
        ((float4*)sW)[i] = ((const float4*)gat_W)[i];
    if (tid < 128) sa[tid] = (tid < 64) ? a_src[tid] : a_dst[tid - 64];

    int nbase = blockIdx.x * 64;
    for (int i = tid; i < 1024; i += 256) {
        int ln = i >> 4, kq = i & 15;
        float4 v = ((const float4*)g_h)[(nbase + ln) * 16 + kq];
        sz[ln][kq * 4 + 0] = v.x; sz[ln][kq * 4 + 1] = v.y;
        sz[ln][kq * 4 + 2] = v.z; sz[ln][kq * 4 + 3] = v.w;
    }
    if (tid < 192) {
        int ln = tid / 3, f = tid % 3;
        int nid = nbase + ln;
        int b = nid >> 12, n = nid & 4095;
        sz[ln][64 + f] = x[((b * TT + t) * NN + n) * 3 + f];
    }
    __syncthreads();

    int j4 = (tid & 15) * 4;
    int g  = tid >> 4;
    float acc[4][4];
    #pragma unroll
    for (int i = 0; i < 4; i++)
        #pragma unroll
        for (int c = 0; c < 4; c++) acc[i][c] = 0.0f;

    #pragma unroll 4
    for (int k = 0; k < 67; k++) {
        float4 w = *(float4*)&sW[k * 64 + j4];
        #pragma unroll
        for (int i = 0; i < 4; i++) {
            float z = sz[g * 4 + i][k];
            acc[i][0] += z * w.x; acc[i][1] += z * w.y;
            acc[i][2] += z * w.z; acc[i][3] += z * w.w;
        }
    }

    #pragma unroll
    for (int i = 0; i < 4; i++) {
        int nid = nbase + g * 4 + i;
        int b = nid >> 12, n = nid & 4095;
        int p = j4 >> 1;
        ((__half2*)g_hgat4)[(n * 32 + p) * 8 + b]     = __floats2half2_rn(acc[i][0], acc[i][1]);
        ((__half2*)g_hgat4)[(n * 32 + p + 1) * 8 + b] = __floats2half2_rn(acc[i][2], acc[i][3]);

        float v1 = acc[i][0] * sa[j4]      + acc[i][1] * sa[j4 + 1]
                 + acc[i][2] * sa[j4 + 2]  + acc[i][3] * sa[j4 + 3];
        float v2 = acc[i][0] * sa[64 + j4]     + acc[i][1] * sa[64 + j4 + 1]
                 + acc[i][2] * sa[64 + j4 + 2] + acc[i][3] * sa[64 + j4 + 3];
        #pragma unroll
        for (int o2 = 8; o2 > 0; o2 >>= 1) {
            v1 += __shfl_down_sync(0xFFFFFFFFu, v1, o2, 16);
            v2 += __shfl_down_sync(0xFFFFFFFFu, v2, o2, 16);
        }
        if ((tid & 15) == 0) { g_est[n * 8 + b] = v1 * LOG2E; g_edt[n * 8 + b] = v2 * LOG2E; }
    }
}

// ---------------- kernel 6: GRU cell (+ fused output projection on last step) ----
// 256 threads, 32 nodes/block (round-10 proven float4 version).
__global__ __launch_bounds__(256) void gru_kernel(
    const float* __restrict__ x,
    const float* __restrict__ W1, const float* __restrict__ b1,
    const float* __restrict__ W2, const float* __restrict__ b2,
    const float* __restrict__ oW, const float* __restrict__ ob,
    float* __restrict__ out, int t, int last)
{
    __shared__ float sW[67 * 128];    // 34.3 KB, phase2 reuses lower 67*64
    __shared__ float sz[32][68];      // [s (0..63), x (64..66)]
    __shared__ float sb1[128];
    __shared__ float sb2[64];
    __shared__ float sow[192];
    __shared__ float sob[4];
    float* srs = sW + 67 * 64;                 // r*s, aliases dead upper W1
    float* su  = sW + 67 * 64 + 32 * 64;       // u

    int tid = threadIdx.x;
    int nbase = blockIdx.x * 32;

    for (int i = tid; i < 2144; i += 256)
        ((float4*)sW)[i] = ((const float4*)W1)[i];
    if (tid < 128) sb1[tid] = b1[tid];
    if (tid < 64)  sb2[tid] = b2[tid];
    if (last) {
        if (tid < 192) sow[tid] = oW[tid];
        if (tid < 3)   sob[tid] = ob[tid];
    }

    for (int i = tid; i < 512; i += 256) {
        int ln = i >> 4, kq = (i & 15) * 4;
        float4 v = ((const float4*)g_s)[(nbase + ln) * 16 + (i & 15)];
        sz[ln][kq + 0] = v.x; sz[ln][kq + 1] = v.y;
        sz[ln][kq + 2] = v.z; sz[ln][kq + 3] = v.w;
    }
    if (tid < 96) {
        int ln = tid / 3, f = tid % 3;
        int nid = nbase + ln;
        int b = nid >> 12, n = nid & 4095;
        sz[ln][64 + f] = x[((b * TT + t) * NN + n) * 3 + f];
    }
    __syncthreads();

    // ---- phase 1: ru = sigmoid([x, s] @ W1 + b1) ----  (W1 rows: 0..2 x, 3..66 s)
    int j4 = (tid & 31) * 4;
    int g  = tid >> 5;
    float acc[4][4];
    #pragma unroll
    for (int i = 0; i < 4; i++)
        #pragma unroll
        for (int c = 0; c < 4; c++) acc[i][c] = sb1[j4 + c];

    #pragma unroll
    for (int f = 0; f < 3; f++) {
        float4 wv = *(float4*)&sW[f * 128 + j4];
        #pragma unroll
        for (int i = 0; i < 4; i++) {
            float z = sz[g * 4 + i][64 + f];
            acc[i][0] += z * wv.x; acc[i][1] += z * wv.y;
            acc[i][2] += z * wv.z; acc[i][3] += z * wv.w;
        }
    }
    #pragma unroll 4
    for (int k = 0; k < 64; k++) {
        float4 wv = *(float4*)&sW[(3 + k) * 128 + j4];
        #pragma unroll
        for (int i = 0; i < 4; i++) {
            float z = sz[g * 4 + i][k];
            acc[i][0] += z * wv.x; acc[i][1] += z * wv.y;
            acc[i][2] += z * wv.z; acc[i][3] += z * wv.w;
        }
    }
    __syncthreads();

    #pragma unroll
    for (int i = 0; i < 4; i++) {
        int n = g * 4 + i;
        #pragma unroll
        for (int c = 0; c < 4; c++) {
            float v = 1.0f / (1.0f + __expf(-acc[i][c]));
            if (j4 < 64) srs[n * 64 + j4 + c] = v * sz[n][j4 + c];
            else         su[n * 64 + (j4 - 64) + c] = v;
        }
    }
    for (int i = tid; i < 1072; i += 256)
        ((float4*)sW)[i] = ((const float4*)W2)[i];
    __syncthreads();

    // ---- phase 2: c = tanh([x, r*s] @ W2 + b2); h = u*s + (1-u)*c ----
    int j4b = (tid & 15) * 4;
    int g2  = tid >> 4;
    float a2[2][4];
    #pragma unroll
    for (int i = 0; i < 2; i++)
        #pragma unroll
        for (int c = 0; c < 4; c++) a2[i][c] = sb2[j4b + c];

    #pragma unroll
    for (int f = 0; f < 3; f++) {
        float4 wv = *(float4*)&sW[f * 64 + j4b];
        #pragma unroll
        for (int i = 0; i < 2; i++) {
            float z = sz[g2 * 2 + i][64 + f];
            a2[i][0] += z * wv.x; a2[i][1] += z * wv.y;
            a2[i][2] += z * wv.z; a2[i][3] += z * wv.w;
        }
    }
    #pragma unroll 4
    for (int k = 0; k < 64; k++) {
        float4 wv = *(float4*)&sW[(3 + k) * 64 + j4b];
        #pragma unroll
        for (int i = 0; i < 2; i++) {
            float z = srs[(g2 * 2 + i) * 64 + k];
            a2[i][0] += z * wv.x; a2[i][1] += z * wv.y;
            a2[i][2] += z * wv.z; a2[i][3] += z * wv.w;
        }
    }

    float hh[2][4];
    #pragma unroll
    for (int i = 0; i < 2; i++) {
        int n = g2 * 2 + i;
        #pragma unroll
        for (int c = 0; c < 4; c++) {
            float cc = tanhf(a2[i][c]);
            float u = su[n * 64 + j4b + c];
            float s = sz[n][j4b + c];
            hh[i][c] = u * s + (1.0f - u) * cc;
        }
    }

    if (!last) {
        #pragma unroll
        for (int i = 0; i < 2; i++) {
            int nid = nbase + g2 * 2 + i;
            ((float4*)g_h)[nid * 16 + (j4b >> 2)] =
                make_float4(hh[i][0], hh[i][1], hh[i][2], hh[i][3]);
        }
    } else {
        __syncthreads();   // all reads of sz(s) done before overwrite with h
        #pragma unroll
        for (int i = 0; i < 2; i++)
            #pragma unroll
            for (int c = 0; c < 4; c++) sz[g2 * 2 + i][j4b + c] = hh[i][c];
        __syncthreads();
        if (tid < 96) {
            int ln = tid / 3, d = tid % 3;
            float acc3 = sob[d];
            #pragma unroll 8
            for (int k = 0; k < 64; k++) acc3 += sz[ln][k] * sow[k * 3 + d];
            out[(nbase + ln) * 3 + d] = acc3;
        }
    }
}

// ---------------- launch ----------------
extern "C" void kernel_launch(void* const* d_in, const int* in_sizes, int n_in,
                              void* d_out, int out_size)
{
    const float* x       = (const float*)d_in[0];
    const int*   src     = (const int*)  d_in[1];
    const int*   dst     = (const int*)  d_in[2];
    const float* gat_W   = (const float*)d_in[3];
    const float* a_src   = (const float*)d_in[4];
    const float* a_dst   = (const float*)d_in[5];
    const float* gat_b   = (const float*)d_in[6];
    const float* gru1_W  = (const float*)d_in[7];
    const float* gru1_b  = (const float*)d_in[8];
    const float* gru2_W  = (const float*)d_in[9];
    const float* gru2_b  = (const float*)d_in[10];
    const float* out_W   = (const float*)d_in[11];
    const float* out_b   = (const float*)d_in[12];
    float* out = (float*)d_out;

    gat0_count_kernel<<<4096 + 272, 256>>>(x, gat_W, a_src, a_dst, dst);
    scan_kernel<<<1, 1024>>>();
    scatter_kernel<<<(EF + 255) / 256, 256>>>(src, dst);

    for (int t = 0; t < TT; t++) {
        gat_gather_kernel<<<NN / 4, 256>>>(gat_b);
        gru_kernel<<<BN / 32, 256>>>(x, gru1_W, gru1_b, gru2_W, gru2_b,
                                     out_W, out_b, out, t, (t == TT - 1) ? 1 : 0);
        if (t < TT - 1)
            gat_node_kernel<<<BN / 64, 256>>>(x, gat_W, a_src, a_dst, t + 1);
    }
}

// round 14
// speedup vs baseline: 1.4715x; 1.3984x over previous
#include <cuda_runtime.h>
#include <cuda_fp16.h>
#include <cuda_bf16.h>

#define BB 8
#define TT 4
#define NN 4096
#define EE 65536
#define EF (EE + NN)          // edges + self loops = 69632
#define BN (BB * NN)          // 32768
#define LOG2E 1.44269504f

// ---------------- device scratch ----------------
// hgat in fp16, layout [n][colpair p (32)][batch b (8)] as half2; uint4 = 4 batches
__device__ uint4   g_hgat4[NN * 32 * 2];   // 4 MB
__device__ float   g_est[NN * BB];         // es * log2e, transposed [n*8 + b]
__device__ float   g_edt[NN * BB];         // ed * log2e, transposed [n*8 + b]
__device__ float   g_s[BN * 64];           // GAT output, [b*NN+n][64]
__device__ float   g_h[BN * 64];           // GRU hidden state
__device__ int     g_cnt[NN];
__device__ int     g_cur[NN];
__device__ int     g_off[NN + 1];
__device__ int     g_srcs[EF];

__device__ __forceinline__ float ex2(float x) {
    float r; asm("ex2.approx.f32 %0, %1;" : "=f"(r) : "f"(x)); return r;
}
__device__ __forceinline__ unsigned sptr(const void* p) {
    return (unsigned)__cvta_generic_to_shared(p);
}
__device__ __forceinline__ void ldmA(unsigned addr, unsigned& a0, unsigned& a1,
                                     unsigned& a2, unsigned& a3) {
    asm volatile("ldmatrix.sync.aligned.m8n8.x4.shared.b16 {%0,%1,%2,%3}, [%4];"
        : "=r"(a0), "=r"(a1), "=r"(a2), "=r"(a3) : "r"(addr));
}
__device__ __forceinline__ void ldmBT(unsigned addr, unsigned& b0, unsigned& b1) {
    asm volatile("ldmatrix.sync.aligned.m8n8.x2.trans.shared.b16 {%0,%1}, [%2];"
        : "=r"(b0), "=r"(b1) : "r"(addr));
}
__device__ __forceinline__ void mma16816(float& c0, float& c1, float& c2, float& c3,
    unsigned a0, unsigned a1, unsigned a2, unsigned a3, unsigned b0, unsigned b1) {
    asm volatile("mma.sync.aligned.m16n8k16.row.col.f32.f16.f16.f32 "
        "{%0,%1,%2,%3}, {%4,%5,%6,%7}, {%8,%9}, {%0,%1,%2,%3};"
        : "+f"(c0), "+f"(c1), "+f"(c2), "+f"(c3)
        : "r"(a0), "r"(a1), "r"(a2), "r"(a3), "r"(b0), "r"(b1));
}

// ---------------- kernel 1: edge count + GAT step-0 node transform ----------------
__global__ __launch_bounds__(256) void gat0_count_kernel(
    const float* __restrict__ x, const float* __restrict__ gat_W,
    const float* __restrict__ a_src, const float* __restrict__ a_dst,
    const int* __restrict__ dst)
{
    if (blockIdx.x >= 4096) {
        int i = (blockIdx.x - 4096) * 256 + threadIdx.x;
        if (i < EF) {
            int d = (i < EE) ? dst[i] : (i - EE);
            atomicAdd(&g_cnt[d], 1);
        }
        return;
    }
    int w = threadIdx.x >> 5, lane = threadIdx.x & 31;
    int nid = blockIdx.x * 8 + w;
    int b = nid >> 12, n = nid & 4095;
    const float* xp = &x[((b * TT + 0) * NN + n) * 3];
    float x0 = __ldg(xp), x1 = __ldg(xp + 1), x2 = __ldg(xp + 2);
    int c0 = 2 * lane, c1 = 2 * lane + 1;
    float h0 = x0 * __ldg(&gat_W[64 * 64 + c0]) + x1 * __ldg(&gat_W[65 * 64 + c0])
             + x2 * __ldg(&gat_W[66 * 64 + c0]);
    float h1 = x0 * __ldg(&gat_W[64 * 64 + c1]) + x1 * __ldg(&gat_W[65 * 64 + c1])
             + x2 * __ldg(&gat_W[66 * 64 + c1]);
    ((__half2*)g_hgat4)[(n * 32 + lane) * 8 + b] = __floats2half2_rn(h0, h1);
    float es = h0 * __ldg(&a_src[c0]) + h1 * __ldg(&a_src[c1]);
    float ed = h0 * __ldg(&a_dst[c0]) + h1 * __ldg(&a_dst[c1]);
    #pragma unroll
    for (int o = 16; o > 0; o >>= 1) {
        es += __shfl_down_sync(0xFFFFFFFFu, es, o);
        ed += __shfl_down_sync(0xFFFFFFFFu, ed, o);
    }
    if (lane == 0) { g_est[n * 8 + b] = es * LOG2E; g_edt[n * 8 + b] = ed * LOG2E; }
}

// ---------------- kernel 2: prefix scan (+ re-zero counters for graph replay) ----
__global__ void scan_kernel() {
    __shared__ int tsum[1024];
    int tid = threadIdx.x;
    int base = tid * 4;
    int c0 = g_cnt[base + 0], c1 = g_cnt[base + 1];
    int c2 = g_cnt[base + 2], c3 = g_cnt[base + 3];
    int sum4 = c0 + c1 + c2 + c3;
    tsum[tid] = sum4;
    __syncthreads();
    for (int ofs = 1; ofs < 1024; ofs <<= 1) {
        int add = 0;
        if (tid >= ofs) add = tsum[tid - ofs];
        __syncthreads();
        tsum[tid] += add;
        __syncthreads();
    }
    int excl = tsum[tid] - sum4;
    g_off[base + 0] = excl;
    g_off[base + 1] = excl + c0;
    g_off[base + 2] = excl + c0 + c1;
    g_off[base + 3] = excl + c0 + c1 + c2;
    if (tid == 1023) g_off[NN] = tsum[1023];
    g_cnt[base + 0] = 0; g_cnt[base + 1] = 0; g_cnt[base + 2] = 0; g_cnt[base + 3] = 0;
    g_cur[base + 0] = 0; g_cur[base + 1] = 0; g_cur[base + 2] = 0; g_cur[base + 3] = 0;
}

// ---------------- kernel 3: CSR scatter ----------------
__global__ void scatter_kernel(const int* __restrict__ src, const int* __restrict__ dst) {
    int i = blockIdx.x * blockDim.x + threadIdx.x;
    if (i >= EF) return;
    int s, d;
    if (i < EE) { s = src[i]; d = dst[i]; }
    else        { s = i - EE; d = i - EE; }
    int pos = g_off[d] + atomicAdd(&g_cur[d], 1);
    g_srcs[pos] = s;
}

// ---------------- kernel 4: gather, 4 batches/warp, depth-2 pipeline -------------
__global__ __launch_bounds__(256) void gat_gather_kernel(const float* __restrict__ gat_b)
{
    int gw = blockIdx.x * 8 + (threadIdx.x >> 5);    // 0..8191
    int n = gw >> 1, bg = (gw & 1) * 4, bq = gw & 1;
    int lane = threadIdx.x & 31;

    float4 ed4 = *(const float4*)&g_edt[n * 8 + bg];
    float edv[4] = {ed4.x, ed4.y, ed4.z, ed4.w};
    float S[4], a0[4], a1[4];
    #pragma unroll
    for (int b = 0; b < 4; b++) { S[b] = 0.0f; a0[b] = 0.0f; a1[b] = 0.0f; }

    int e0 = g_off[n];
    int en1 = g_off[n + 1] - 1;
    int cnt = en1 - e0 + 1;
    int hofs = lane * 2 + bq;

    int sA = __ldg(&g_srcs[e0]);
    int s1 = __ldg(&g_srcs[min(e0 + 1, en1)]);
    int sC = __ldg(&g_srcs[min(e0 + 2, en1)]);
    int sD = __ldg(&g_srcs[min(e0 + 3, en1)]);
    float4 esv[2]; uint4 hv[2];
    esv[0] = *(const float4*)&g_est[sA * 8 + bg];
    hv[0]  = __ldg(&g_hgat4[sA * 64 + hofs]);
    esv[1] = *(const float4*)&g_est[s1 * 8 + bg];
    hv[1]  = __ldg(&g_hgat4[s1 * 64 + hofs]);

    for (int i = 0; i < cnt; i++) {
        int cur = i & 1;
        float4 ces = esv[cur];
        uint4  ch  = hv[cur];
        esv[cur] = *(const float4*)&g_est[sC * 8 + bg];
        hv[cur]  = __ldg(&g_hgat4[sC * 64 + hofs]);
        sC = sD;
        sD = __ldg(&g_srcs[min(e0 + i + 4, en1)]);

        float esvv[4] = {ces.x, ces.y, ces.z, ces.w};
        unsigned hw[4] = {ch.x, ch.y, ch.z, ch.w};
        #pragma unroll
        for (int b = 0; b < 4; b++) {
            float ev = esvv[b] + edv[b];
            ev = fmaxf(ev, 0.2f * ev);
            float w = ex2(ev);
            float2 f = __half22float2(*(__half2*)&hw[b]);
            S[b] += w; a0[b] += w * f.x; a1[b] += w * f.y;
        }
    }
    float gb0 = __ldg(&gat_b[2 * lane]), gb1 = __ldg(&gat_b[2 * lane + 1]);
    #pragma unroll
    for (int b = 0; b < 4; b++) {
        float inv = 1.0f / S[b];
        ((float2*)(g_s + ((bg + b) * NN + n) * 64))[lane] =
            make_float2(a0[b] * inv + gb0, a1[b] * inv + gb1);
    }
}

// ---------------- kernel 5: GAT node transform (steps 1..3) ----------------
__global__ __launch_bounds__(256) void gat_node_kernel(
    const float* __restrict__ x, const float* __restrict__ gat_W,
    const float* __restrict__ a_src, const float* __restrict__ a_dst, int t)
{
    __shared__ float sW[67 * 64];
    __shared__ float sz[64][68];
    __shared__ float sa[128];

    int tid = threadIdx.x;
    for (int i = tid; i < 1072; i += 256)
        ((float4*)sW)[i] = ((const float4*)gat_W)[i];
    if (tid < 128) sa[tid] = (tid < 64) ? a_src[tid] : a_dst[tid - 64];

    int nbase = blockIdx.x * 64;
    for (int i = tid; i < 1024; i += 256) {
        int ln = i >> 4, kq = i & 15;
        float4 v = ((const float4*)g_h)[(nbase + ln) * 16 + kq];
        sz[ln][kq * 4 + 0] = v.x; sz[ln][kq * 4 + 1] = v.y;
        sz[ln][kq * 4 + 2] = v.z; sz[ln][kq * 4 + 3] = v.w;
    }
    if (tid < 192) {
        int ln = tid / 3, f = tid % 3;
        int nid = nbase + ln;
        int b = nid >> 12, n = nid & 4095;
        sz[ln][64 + f] = x[((b * TT + t) * NN + n) * 3 + f];
    }
    __syncthreads();

    int j4 = (tid & 15) * 4;
    int g  = tid >> 4;
    float acc[4][4];
    #pragma unroll
    for (int i = 0; i < 4; i++)
        #pragma unroll
        for (int c = 0; c < 4; c++) acc[i][c] = 0.0f;

    #pragma unroll 4
    for (int k = 0; k < 67; k++) {
        float4 w = *(float4*)&sW[k * 64 + j4];
        #pragma unroll
        for (int i = 0; i < 4; i++) {
            float z = sz[g * 4 + i][k];
            acc[i][0] += z * w.x; acc[i][1] += z * w.y;
            acc[i][2] += z * w.z; acc[i][3] += z * w.w;
        }
    }

    #pragma unroll
    for (int i = 0; i < 4; i++) {
        int nid = nbase + g * 4 + i;
        int b = nid >> 12, n = nid & 4095;
        int p = j4 >> 1;
        ((__half2*)g_hgat4)[(n * 32 + p) * 8 + b]     = __floats2half2_rn(acc[i][0], acc[i][1]);
        ((__half2*)g_hgat4)[(n * 32 + p + 1) * 8 + b] = __floats2half2_rn(acc[i][2], acc[i][3]);

        float v1 = acc[i][0] * sa[j4]      + acc[i][1] * sa[j4 + 1]
                 + acc[i][2] * sa[j4 + 2]  + acc[i][3] * sa[j4 + 3];
        float v2 = acc[i][0] * sa[64 + j4]     + acc[i][1] * sa[64 + j4 + 1]
                 + acc[i][2] * sa[64 + j4 + 2] + acc[i][3] * sa[64 + j4 + 3];
        #pragma unroll
        for (int o2 = 8; o2 > 0; o2 >>= 1) {
            v1 += __shfl_down_sync(0xFFFFFFFFu, v1, o2, 16);
            v2 += __shfl_down_sync(0xFFFFFFFFu, v2, o2, 16);
        }
        if ((tid & 15) == 0) { g_est[n * 8 + b] = v1 * LOG2E; g_edt[n * 8 + b] = v2 * LOG2E; }
    }
}

// ---------------- kernel 6: GRU cell via fp16 mma.sync (fp32 accum) --------------
// 256 threads = 8 warps, 32 nodes/block. K padded 67->80 (zeros).
// phase1: [32x80] @ W1[80x128]; warp w owns n = w*16..w*16+15.
// phase2: [32x80] @ W2[80x64];  warp w owns n = w*8..w*8+7.
__global__ __launch_bounds__(256) void gru_kernel(
    const float* __restrict__ x,
    const float* __restrict__ W1, const float* __restrict__ b1,
    const float* __restrict__ W2, const float* __restrict__ b2,
    const float* __restrict__ oW, const float* __restrict__ ob,
    float* __restrict__ out, int t, int last)
{
    __shared__ __align__(16) __half sz[32][88];     // A1: x(0..2), s(3..66), 0 pad
    __shared__ __align__(16) __half szrs[32][88];   // A2: x(0..2), r*s(3..66), 0 pad
    __shared__ __align__(16) __half sW[80][136];    // W1 fp16, then W2 fp16
    __shared__ float su[32][64];                    // u, then h (last step)
    __shared__ float sb1[128];
    __shared__ float sb2[64];
    __shared__ float sow[192];
    __shared__ float sob[4];

    int tid = threadIdx.x;
    int lane = tid & 31;
    int w = tid >> 5;
    int nbase = blockIdx.x * 32;

    // W1 -> fp16 smem (rows 67..79 zero)
    for (int i = tid; i < 80 * 32; i += 256) {
        int k = i >> 5, n4 = (i & 31) * 4;
        __half2 h01, h23;
        if (k < 67) {
            float4 v = *(const float4*)&W1[k * 128 + n4];
            h01 = __floats2half2_rn(v.x, v.y);
            h23 = __floats2half2_rn(v.z, v.w);
        } else {
            h01 = __floats2half2_rn(0.f, 0.f); h23 = h01;
        }
        *(__half2*)&sW[k][n4]     = h01;
        *(__half2*)&sW[k][n4 + 2] = h23;
    }
    if (tid < 128) sb1[tid] = b1[tid];
    if (tid < 64)  sb2[tid] = b2[tid];
    if (last) {
        if (tid < 192) sow[tid] = oW[tid];
        if (tid < 3)   sob[tid] = ob[tid];
    }

    // s -> sz[.][3..66] fp16
    for (int i = tid; i < 512; i += 256) {
        int ln = i >> 4, q = i & 15;
        float4 v = ((const float4*)g_s)[(nbase + ln) * 16 + q];
        int kb = 3 + q * 4;
        sz[ln][kb]     = __float2half(v.x);
        sz[ln][kb + 1] = __float2half(v.y);
        sz[ln][kb + 2] = __float2half(v.z);
        sz[ln][kb + 3] = __float2half(v.w);
    }
    // zero pads k=67..87 in both A buffers
    for (int i = tid; i < 32 * 21; i += 256) {
        int ln = i / 21, k = 67 + (i % 21);
        sz[ln][k]   = __float2half(0.f);
        szrs[ln][k] = __float2half(0.f);
    }
    // x -> k 0..2 in both A buffers
    if (tid < 96) {
        int ln = tid / 3, f = tid % 3;
        int nid = nbase + ln;
        int b = nid >> 12, n = nid & 4095;
        __half hx = __float2half(x[((b * TT + t) * NN + n) * 3 + f]);
        sz[ln][f]   = hx;
        szrs[ln][f] = hx;
    }
    __syncthreads();

    // ---- phase 1 MMA ----
    int nb = w * 16;
    float acc[2][2][4];
    #pragma unroll
    for (int m = 0; m < 2; m++)
        #pragma unroll
        for (int nt = 0; nt < 2; nt++) {
            int j0 = nb + nt * 8 + 2 * (lane & 3);
            acc[m][nt][0] = sb1[j0];     acc[m][nt][1] = sb1[j0 + 1];
            acc[m][nt][2] = sb1[j0];     acc[m][nt][3] = sb1[j0 + 1];
        }
    #pragma unroll
    for (int kb = 0; kb < 5; kb++) {
        unsigned a[2][4];
        #pragma unroll
        for (int m = 0; m < 2; m++)
            ldmA(sptr(&sz[m * 16 + (lane & 15)][kb * 16 + (lane >> 4) * 8]),
                 a[m][0], a[m][1], a[m][2], a[m][3]);
        #pragma unroll
        for (int nt = 0; nt < 2; nt++) {
            unsigned b0, b1v;
            ldmBT(sptr(&sW[kb * 16 + (lane & 15)][nb + nt * 8]), b0, b1v);
            #pragma unroll
            for (int m = 0; m < 2; m++)
                mma16816(acc[m][nt][0], acc[m][nt][1], acc[m][nt][2], acc[m][nt][3],
                         a[m][0], a[m][1], a[m][2], a[m][3], b0, b1v);
        }
    }

    // epilogue 1: sigmoid -> r*s (cols<64) / u (cols>=64)
    #pragma unroll
    for (int m = 0; m < 2; m++)
        #pragma unroll
        for (int nt = 0; nt < 2; nt++) {
            int j0 = nb + nt * 8 + 2 * (lane & 3);
            #pragma unroll
            for (int rr = 0; rr < 2; rr++) {
                int node = m * 16 + (lane >> 2) + rr * 8;
                float s0 = 1.f / (1.f + __expf(-acc[m][nt][rr * 2 + 0]));
                float s1 = 1.f / (1.f + __expf(-acc[m][nt][rr * 2 + 1]));
                if (j0 < 64) {
                    szrs[node][3 + j0]     = __float2half(s0 * __half2float(sz[node][3 + j0]));
                    szrs[node][3 + j0 + 1] = __float2half(s1 * __half2float(sz[node][3 + j0 + 1]));
                } else {
                    su[node][j0 - 64]     = s0;
                    su[node][j0 - 63]     = s1;
                }
            }
        }
    __syncthreads();   // all W1 reads + szrs/su writes complete

    // W2 -> fp16 smem (rows 67..79 zero)
    for (int i = tid; i < 80 * 16; i += 256) {
        int k = i >> 4, n4 = (i & 15) * 4;
        __half2 h01, h23;
        if (k < 67) {
            float4 v = *(const float4*)&W2[k * 64 + n4];
            h01 = __floats2half2_rn(v.x, v.y);
            h23 = __floats2half2_rn(v.z, v.w);
        } else {
            h01 = __floats2half2_rn(0.f, 0.f); h23 = h01;
        }
        *(__half2*)&sW[k][n4]     = h01;
        *(__half2*)&sW[k][n4 + 2] = h23;
    }
    __syncthreads();

    // ---- phase 2 MMA ----
    int nb2 = w * 8;
    float a2c[2][4];
    {
        int j0 = nb2 + 2 * (lane & 3);
        #pragma unroll
        for (int m = 0; m < 2; m++) {
            a2c[m][0] = sb2[j0];     a2c[m][1] = sb2[j0 + 1];
            a2c[m][2] = sb2[j0];     a2c[m][3] = sb2[j0 + 1];
        }
    }
    #pragma unroll
    for (int kb = 0; kb < 5; kb++) {
        unsigned b0, b1v;
        ldmBT(sptr(&sW[kb * 16 + (lane & 15)][nb2]), b0, b1v);
        #pragma unroll
        for (int m = 0; m < 2; m++) {
            unsigned a[4];
            ldmA(sptr(&szrs[m * 16 + (lane & 15)][kb * 16 + (lane >> 4) * 8]),
                 a[0], a[1], a[2], a[3]);
            mma16816(a2c[m][0], a2c[m][1], a2c[m][2], a2c[m][3],
                     a[0], a[1], a[2], a[3], b0, b1v);
        }
    }

    // epilogue 2: c = tanh, h = u*s + (1-u)*c
    {
        int j0 = nb2 + 2 * (lane & 3);
        #pragma unroll
        for (int m = 0; m < 2; m++)
            #pragma unroll
            for (int rr = 0; rr < 2; rr++) {
                int node = m * 16 + (lane >> 2) + rr * 8;
                float cc0 = tanhf(a2c[m][rr * 2 + 0]);
                float cc1 = tanhf(a2c[m][rr * 2 + 1]);
                float u0 = su[node][j0], u1 = su[node][j0 + 1];
                float s0 = __half2float(sz[node][3 + j0]);
                float s1 = __half2float(sz[node][3 + j0 + 1]);
                float h0 = u0 * s0 + (1.f - u0) * cc0;
                float h1 = u1 * s1 + (1.f - u1) * cc1;
                if (!last) {
                    *(float2*)&g_h[(nbase + node) * 64 + j0] = make_float2(h0, h1);
                } else {
                    su[node][j0] = h0; su[node][j0 + 1] = h1;  // same-thread RW
                }
            }
    }
    if (last) {
        __syncthreads();
        if (tid < 96) {
            int ln = tid / 3, d = tid % 3;
            float acc3 = sob[d];
            #pragma unroll 8
            for (int k = 0; k < 64; k++) acc3 += su[ln][k] * sow[k * 3 + d];
            out[(nbase + ln) * 3 + d] = acc3;
        }
    }
}

// ---------------- launch ----------------
extern "C" void kernel_launch(void* const* d_in, const int* in_sizes, int n_in,
                              void* d_out, int out_size)
{
    const float* x       = (const float*)d_in[0];
    const int*   src     = (const int*)  d_in[1];
    const int*   dst     = (const int*)  d_in[2];
    const float* gat_W   = (const float*)d_in[3];
    const float* a_src   = (const float*)d_in[4];
    const float* a_dst   = (const float*)d_in[5];
    const float* gat_b   = (const float*)d_in[6];
    const float* gru1_W  = (const float*)d_in[7];
    const float* gru1_b  = (const float*)d_in[8];
    const float* gru2_W  = (const float*)d_in[9];
    const float* gru2_b  = (const float*)d_in[10];
    const float* out_W   = (const float*)d_in[11];
    const float* out_b   = (const float*)d_in[12];
    float* out = (float*)d_out;

    gat0_count_kernel<<<4096 + 272, 256>>>(x, gat_W, a_src, a_dst, dst);
    scan_kernel<<<1, 1024>>>();
    scatter_kernel<<<(EF + 255) / 256, 256>>>(src, dst);

    for (int t = 0; t < TT; t++) {
        gat_gather_kernel<<<NN / 4, 256>>>(gat_b);
        gru_kernel<<<BN / 32, 256>>>(x, gru1_W, gru1_b, gru2_W, gru2_b,
                                     out_W, out_b, out, t, (t == TT - 1) ? 1 : 0);
        if (t < TT - 1)
            gat_node_kernel<<<BN / 64, 256>>>(x, gat_W, a_src, a_dst, t + 1);
    }
}

// round 15
// speedup vs baseline: 1.6405x; 1.1149x over previous
#include <cuda_runtime.h>
#include <cuda_fp16.h>
#include <cuda_bf16.h>

#define BB 8
#define TT 4
#define NN 4096
#define EE 65536
#define EF (EE + NN)          // edges + self loops = 69632
#define BN (BB * NN)          // 32768
#define LOG2E 1.44269504f

// ---------------- device scratch ----------------
// hgat in fp16, layout [n][colpair p (32)][batch b (8)] as half2; uint4 = 4 batches
__device__ uint4   g_hgat4[NN * 32 * 2];   // 4 MB
__device__ float   g_est[NN * BB];         // es * log2e, transposed [n*8 + b]
__device__ float   g_edt[NN * BB];         // ed * log2e, transposed [n*8 + b]
__device__ float   g_s[BN * 64];           // GAT output, [b*NN+n][64]
__device__ int     g_cnt[NN];
__device__ int     g_cur[NN];
__device__ int     g_off[NN + 1];
__device__ int     g_srcs[EF];

__device__ __forceinline__ float ex2(float x) {
    float r; asm("ex2.approx.f32 %0, %1;" : "=f"(r) : "f"(x)); return r;
}
__device__ __forceinline__ unsigned sptr(const void* p) {
    return (unsigned)__cvta_generic_to_shared(p);
}
__device__ __forceinline__ void ldmA(unsigned addr, unsigned& a0, unsigned& a1,
                                     unsigned& a2, unsigned& a3) {
    asm volatile("ldmatrix.sync.aligned.m8n8.x4.shared.b16 {%0,%1,%2,%3}, [%4];"
        : "=r"(a0), "=r"(a1), "=r"(a2), "=r"(a3) : "r"(addr));
}
__device__ __forceinline__ void ldmBT(unsigned addr, unsigned& b0, unsigned& b1) {
    asm volatile("ldmatrix.sync.aligned.m8n8.x2.trans.shared.b16 {%0,%1}, [%2];"
        : "=r"(b0), "=r"(b1) : "r"(addr));
}
__device__ __forceinline__ void mma16816(float& c0, float& c1, float& c2, float& c3,
    unsigned a0, unsigned a1, unsigned a2, unsigned a3, unsigned b0, unsigned b1) {
    asm volatile("mma.sync.aligned.m16n8k16.row.col.f32.f16.f16.f32 "
        "{%0,%1,%2,%3}, {%4,%5,%6,%7}, {%8,%9}, {%0,%1,%2,%3};"
        : "+f"(c0), "+f"(c1), "+f"(c2), "+f"(c3)
        : "r"(a0), "r"(a1), "r"(a2), "r"(a3), "r"(b0), "r"(b1));
}

// ---------------- kernel 1: edge count + GAT step-0 node transform ----------------
__global__ __launch_bounds__(256) void gat0_count_kernel(
    const float* __restrict__ x, const float* __restrict__ gat_W,
    const float* __restrict__ a_src, const float* __restrict__ a_dst,
    const int* __restrict__ dst)
{
    if (blockIdx.x >= 4096) {
        int i = (blockIdx.x - 4096) * 256 + threadIdx.x;
        if (i < EF) {
            int d = (i < EE) ? dst[i] : (i - EE);
            atomicAdd(&g_cnt[d], 1);
        }
        return;
    }
    int w = threadIdx.x >> 5, lane = threadIdx.x & 31;
    int nid = blockIdx.x * 8 + w;
    int b = nid >> 12, n = nid & 4095;
    const float* xp = &x[((b * TT + 0) * NN + n) * 3];
    float x0 = __ldg(xp), x1 = __ldg(xp + 1), x2 = __ldg(xp + 2);
    int c0 = 2 * lane, c1 = 2 * lane + 1;
    float h0 = x0 * __ldg(&gat_W[64 * 64 + c0]) + x1 * __ldg(&gat_W[65 * 64 + c0])
             + x2 * __ldg(&gat_W[66 * 64 + c0]);
    float h1 = x0 * __ldg(&gat_W[64 * 64 + c1]) + x1 * __ldg(&gat_W[65 * 64 + c1])
             + x2 * __ldg(&gat_W[66 * 64 + c1]);
    ((__half2*)g_hgat4)[(n * 32 + lane) * 8 + b] = __floats2half2_rn(h0, h1);
    float es = h0 * __ldg(&a_src[c0]) + h1 * __ldg(&a_src[c1]);
    float ed = h0 * __ldg(&a_dst[c0]) + h1 * __ldg(&a_dst[c1]);
    #pragma unroll
    for (int o = 16; o > 0; o >>= 1) {
        es += __shfl_down_sync(0xFFFFFFFFu, es, o);
        ed += __shfl_down_sync(0xFFFFFFFFu, ed, o);
    }
    if (lane == 0) { g_est[n * 8 + b] = es * LOG2E; g_edt[n * 8 + b] = ed * LOG2E; }
}

// ---------------- kernel 2: prefix scan (+ re-zero counters for graph replay) ----
__global__ void scan_kernel() {
    __shared__ int tsum[1024];
    int tid = threadIdx.x;
    int base = tid * 4;
    int c0 = g_cnt[base + 0], c1 = g_cnt[base + 1];
    int c2 = g_cnt[base + 2], c3 = g_cnt[base + 3];
    int sum4 = c0 + c1 + c2 + c3;
    tsum[tid] = sum4;
    __syncthreads();
    for (int ofs = 1; ofs < 1024; ofs <<= 1) {
        int add = 0;
        if (tid >= ofs) add = tsum[tid - ofs];
        __syncthreads();
        tsum[tid] += add;
        __syncthreads();
    }
    int excl = tsum[tid] - sum4;
    g_off[base + 0] = excl;
    g_off[base + 1] = excl + c0;
    g_off[base + 2] = excl + c0 + c1;
    g_off[base + 3] = excl + c0 + c1 + c2;
    if (tid == 1023) g_off[NN] = tsum[1023];
    g_cnt[base + 0] = 0; g_cnt[base + 1] = 0; g_cnt[base + 2] = 0; g_cnt[base + 3] = 0;
    g_cur[base + 0] = 0; g_cur[base + 1] = 0; g_cur[base + 2] = 0; g_cur[base + 3] = 0;
}

// ---------------- kernel 3: CSR scatter ----------------
__global__ void scatter_kernel(const int* __restrict__ src, const int* __restrict__ dst) {
    int i = blockIdx.x * blockDim.x + threadIdx.x;
    if (i >= EF) return;
    int s, d;
    if (i < EE) { s = src[i]; d = dst[i]; }
    else        { s = i - EE; d = i - EE; }
    int pos = g_off[d] + atomicAdd(&g_cur[d], 1);
    g_srcs[pos] = s;
}

// ---------------- kernel 4: gather, 4 batches/warp, depth-2 pipeline -------------
__global__ __launch_bounds__(256) void gat_gather_kernel(const float* __restrict__ gat_b)
{
    int gw = blockIdx.x * 8 + (threadIdx.x >> 5);    // 0..8191
    int n = gw >> 1, bg = (gw & 1) * 4, bq = gw & 1;
    int lane = threadIdx.x & 31;

    float4 ed4 = *(const float4*)&g_edt[n * 8 + bg];
    float edv[4] = {ed4.x, ed4.y, ed4.z, ed4.w};
    float S[4], a0[4], a1[4];
    #pragma unroll
    for (int b = 0; b < 4; b++) { S[b] = 0.0f; a0[b] = 0.0f; a1[b] = 0.0f; }

    int e0 = g_off[n];
    int en1 = g_off[n + 1] - 1;
    int cnt = en1 - e0 + 1;
    int hofs = lane * 2 + bq;

    int sA = __ldg(&g_srcs[e0]);
    int s1 = __ldg(&g_srcs[min(e0 + 1, en1)]);
    int sC = __ldg(&g_srcs[min(e0 + 2, en1)]);
    int sD = __ldg(&g_srcs[min(e0 + 3, en1)]);
    float4 esv[2]; uint4 hv[2];
    esv[0] = *(const float4*)&g_est[sA * 8 + bg];
    hv[0]  = __ldg(&g_hgat4[sA * 64 + hofs]);
    esv[1] = *(const float4*)&g_est[s1 * 8 + bg];
    hv[1]  = __ldg(&g_hgat4[s1 * 64 + hofs]);

    for (int i = 0; i < cnt; i++) {
        int cur = i & 1;
        float4 ces = esv[cur];
        uint4  ch  = hv[cur];
        esv[cur] = *(const float4*)&g_est[sC * 8 + bg];
        hv[cur]  = __ldg(&g_hgat4[sC * 64 + hofs]);
        sC = sD;
        sD = __ldg(&g_srcs[min(e0 + i + 4, en1)]);

        float esvv[4] = {ces.x, ces.y, ces.z, ces.w};
        unsigned hw[4] = {ch.x, ch.y, ch.z, ch.w};
        #pragma unroll
        for (int b = 0; b < 4; b++) {
            float ev = esvv[b] + edv[b];
            ev = fmaxf(ev, 0.2f * ev);
            float w = ex2(ev);
            float2 f = __half22float2(*(__half2*)&hw[b]);
            S[b] += w; a0[b] += w * f.x; a1[b] += w * f.y;
        }
    }
    float gb0 = __ldg(&gat_b[2 * lane]), gb1 = __ldg(&gat_b[2 * lane + 1]);
    #pragma unroll
    for (int b = 0; b < 4; b++) {
        float inv = 1.0f / S[b];
        ((float2*)(g_s + ((bg + b) * NN + n) * 64))[lane] =
            make_float2(a0[b] * inv + gb0, a1[b] * inv + gb1);
    }
}

// ---------------- kernel 5: GRU cell + fused GAT node transform (MMA fp16) -------
// 256 threads = 8 warps, 32 nodes/block. K padded 67->80 (zeros).
// phase1: [32x80] @ W1[80x128]; phase2: [32x80] @ W2[80x64];
// phase3 (t<3): hgat = [h, x(t+1)] @ gat_W via same MMA; es/ed staged smem reduce.
// last step: output projection instead of phase3.
__global__ __launch_bounds__(256) void gru_kernel(
    const float* __restrict__ x,
    const float* __restrict__ W1, const float* __restrict__ b1,
    const float* __restrict__ W2, const float* __restrict__ b2,
    const float* __restrict__ gat_W, const float* __restrict__ a_src,
    const float* __restrict__ a_dst,
    const float* __restrict__ oW, const float* __restrict__ ob,
    float* __restrict__ out, int t, int last)
{
    __shared__ __align__(16) __half sz[32][88];     // A1: x(0..2), s(3..66), 0 pad
    __shared__ __align__(16) __half szrs[32][88];   // A2: x,r*s ; phase3: h,x(t+1)
    __shared__ __align__(16) __half sW[80][136];    // W1 -> W2 -> gat_W (fp16)
    __shared__ float su[32][64];                    // u; phase3: es/ed partials; last: h
    __shared__ float sb1[128];
    __shared__ float sb2[64];
    __shared__ float sa[128];                       // a_src | a_dst
    __shared__ float sow[192];
    __shared__ float sob[4];
    float* sPES = &su[0][0];                        // [32 nodes][32 slots]
    float* sPED = &su[16][0];

    int tid = threadIdx.x;
    int lane = tid & 31;
    int w = tid >> 5;
    int nbase = blockIdx.x * 32;

    // W1 -> fp16 smem (rows 67..79 zero)
    for (int i = tid; i < 80 * 32; i += 256) {
        int k = i >> 5, n4 = (i & 31) * 4;
        __half2 h01, h23;
        if (k < 67) {
            float4 v = *(const float4*)&W1[k * 128 + n4];
            h01 = __floats2half2_rn(v.x, v.y);
            h23 = __floats2half2_rn(v.z, v.w);
        } else {
            h01 = __floats2half2_rn(0.f, 0.f); h23 = h01;
        }
        *(__half2*)&sW[k][n4]     = h01;
        *(__half2*)&sW[k][n4 + 2] = h23;
    }
    if (tid < 128) sb1[tid] = b1[tid];
    if (tid < 64)  sb2[tid] = b2[tid];
    if (last) {
        if (tid < 192) sow[tid] = oW[tid];
        if (tid < 3)   sob[tid] = ob[tid];
    }

    // s -> sz[.][3..66] fp16
    for (int i = tid; i < 512; i += 256) {
        int ln = i >> 4, q = i & 15;
        float4 v = ((const float4*)g_s)[(nbase + ln) * 16 + q];
        int kb = 3 + q * 4;
        sz[ln][kb]     = __float2half(v.x);
        sz[ln][kb + 1] = __float2half(v.y);
        sz[ln][kb + 2] = __float2half(v.z);
        sz[ln][kb + 3] = __float2half(v.w);
    }
    // zero pads k=67..87 in both A buffers
    for (int i = tid; i < 32 * 21; i += 256) {
        int ln = i / 21, k = 67 + (i % 21);
        sz[ln][k]   = __float2half(0.f);
        szrs[ln][k] = __float2half(0.f);
    }
    // x -> k 0..2 in both A buffers
    if (tid < 96) {
        int ln = tid / 3, f = tid % 3;
        int nid = nbase + ln;
        int b = nid >> 12, n = nid & 4095;
        __half hx = __float2half(x[((b * TT + t) * NN + n) * 3 + f]);
        sz[ln][f]   = hx;
        szrs[ln][f] = hx;
    }
    __syncthreads();

    // ---- phase 1 MMA: ru ----
    int nb = w * 16;
    float acc[2][2][4];
    #pragma unroll
    for (int m = 0; m < 2; m++)
        #pragma unroll
        for (int nt = 0; nt < 2; nt++) {
            int j0 = nb + nt * 8 + 2 * (lane & 3);
            acc[m][nt][0] = sb1[j0];     acc[m][nt][1] = sb1[j0 + 1];
            acc[m][nt][2] = sb1[j0];     acc[m][nt][3] = sb1[j0 + 1];
        }
    #pragma unroll
    for (int kb = 0; kb < 5; kb++) {
        unsigned a[2][4];
        #pragma unroll
        for (int m = 0; m < 2; m++)
            ldmA(sptr(&sz[m * 16 + (lane & 15)][kb * 16 + (lane >> 4) * 8]),
                 a[m][0], a[m][1], a[m][2], a[m][3]);
        #pragma unroll
        for (int nt = 0; nt < 2; nt++) {
            unsigned b0, b1v;
            ldmBT(sptr(&sW[kb * 16 + (lane & 15)][nb + nt * 8]), b0, b1v);
            #pragma unroll
            for (int m = 0; m < 2; m++)
                mma16816(acc[m][nt][0], acc[m][nt][1], acc[m][nt][2], acc[m][nt][3],
                         a[m][0], a[m][1], a[m][2], a[m][3], b0, b1v);
        }
    }

    // epilogue 1: sigmoid -> r*s (cols<64) / u (cols>=64)
    #pragma unroll
    for (int m = 0; m < 2; m++)
        #pragma unroll
        for (int nt = 0; nt < 2; nt++) {
            int j0 = nb + nt * 8 + 2 * (lane & 3);
            #pragma unroll
            for (int rr = 0; rr < 2; rr++) {
                int node = m * 16 + (lane >> 2) + rr * 8;
                float s0 = 1.f / (1.f + __expf(-acc[m][nt][rr * 2 + 0]));
                float s1 = 1.f / (1.f + __expf(-acc[m][nt][rr * 2 + 1]));
                if (j0 < 64) {
                    szrs[node][3 + j0]     = __float2half(s0 * __half2float(sz[node][3 + j0]));
                    szrs[node][3 + j0 + 1] = __float2half(s1 * __half2float(sz[node][3 + j0 + 1]));
                } else {
                    su[node][j0 - 64]     = s0;
                    su[node][j0 - 63]     = s1;
                }
            }
        }
    __syncthreads();   // all W1 reads + szrs/su writes complete

    // W2 -> fp16 smem (rows 67..79 zero)
    for (int i = tid; i < 80 * 16; i += 256) {
        int k = i >> 4, n4 = (i & 15) * 4;
        __half2 h01, h23;
        if (k < 67) {
            float4 v = *(const float4*)&W2[k * 64 + n4];
            h01 = __floats2half2_rn(v.x, v.y);
            h23 = __floats2half2_rn(v.z, v.w);
        } else {
            h01 = __floats2half2_rn(0.f, 0.f); h23 = h01;
        }
        *(__half2*)&sW[k][n4]     = h01;
        *(__half2*)&sW[k][n4 + 2] = h23;
    }
    __syncthreads();

    // ---- phase 2 MMA: c ----
    int nb2 = w * 8;
    float a2c[2][4];
    {
        int j0 = nb2 + 2 * (lane & 3);
        #pragma unroll
        for (int m = 0; m < 2; m++) {
            a2c[m][0] = sb2[j0];     a2c[m][1] = sb2[j0 + 1];
            a2c[m][2] = sb2[j0];     a2c[m][3] = sb2[j0 + 1];
        }
    }
    #pragma unroll
    for (int kb = 0; kb < 5; kb++) {
        unsigned b0, b1v;
        ldmBT(sptr(&sW[kb * 16 + (lane & 15)][nb2]), b0, b1v);
        #pragma unroll
        for (int m = 0; m < 2; m++) {
            unsigned a[4];
            ldmA(sptr(&szrs[m * 16 + (lane & 15)][kb * 16 + (lane >> 4) * 8]),
                 a[0], a[1], a[2], a[3]);
            mma16816(a2c[m][0], a2c[m][1], a2c[m][2], a2c[m][3],
                     a[0], a[1], a[2], a[3], b0, b1v);
        }
    }

    // epilogue 2: c = tanh, h = u*s + (1-u)*c  (h kept in registers)
    int j0b = nb2 + 2 * (lane & 3);
    float hreg[2][2][2];
    #pragma unroll
    for (int m = 0; m < 2; m++)
        #pragma unroll
        for (int rr = 0; rr < 2; rr++) {
            int node = m * 16 + (lane >> 2) + rr * 8;
            float cc0 = tanhf(a2c[m][rr * 2 + 0]);
            float cc1 = tanhf(a2c[m][rr * 2 + 1]);
            float u0 = su[node][j0b], u1 = su[node][j0b + 1];
            float s0 = __half2float(sz[node][3 + j0b]);
            float s1 = __half2float(sz[node][3 + j0b + 1]);
            hreg[m][rr][0] = u0 * s0 + (1.f - u0) * cc0;
            hreg[m][rr][1] = u1 * s1 + (1.f - u1) * cc1;
        }
    __syncthreads();   // szrs/su/sW(W2) reads all complete

    if (!last) {
        // ---- phase 3: hgat = [h, x(t+1)] @ gat_W ----
        // h -> szrs rows 0..63 (fp16); x(t+1) -> rows 64..66; 67..79 stay zero
        #pragma unroll
        for (int m = 0; m < 2; m++)
            #pragma unroll
            for (int rr = 0; rr < 2; rr++) {
                int node = m * 16 + (lane >> 2) + rr * 8;
                *(__half2*)&szrs[node][j0b] =
                    __floats2half2_rn(hreg[m][rr][0], hreg[m][rr][1]);
            }
        if (tid < 96) {
            int ln = tid / 3, f = tid % 3;
            int nid = nbase + ln;
            int b = nid >> 12, n = nid & 4095;
            szrs[ln][64 + f] = __float2half(x[((b * TT + t + 1) * NN + n) * 3 + f]);
        }
        // gat_W -> fp16 smem (rows 67..79 already zero from W2 fill)
        for (int i = tid; i < 67 * 16; i += 256) {
            int k = i >> 4, n4 = (i & 15) * 4;
            float4 v = *(const float4*)&gat_W[k * 64 + n4];
            *(__half2*)&sW[k][n4]     = __floats2half2_rn(v.x, v.y);
            *(__half2*)&sW[k][n4 + 2] = __floats2half2_rn(v.z, v.w);
        }
        if (tid < 128) sa[tid] = (tid < 64) ? a_src[tid] : a_dst[tid - 64];
        __syncthreads();

        float gc[2][4];
        #pragma unroll
        for (int m = 0; m < 2; m++)
            #pragma unroll
            for (int c = 0; c < 4; c++) gc[m][c] = 0.f;
        #pragma unroll
        for (int kb = 0; kb < 5; kb++) {
            unsigned b0, b1v;
            ldmBT(sptr(&sW[kb * 16 + (lane & 15)][nb2]), b0, b1v);
            #pragma unroll
            for (int m = 0; m < 2; m++) {
                unsigned a[4];
                ldmA(sptr(&szrs[m * 16 + (lane & 15)][kb * 16 + (lane >> 4) * 8]),
                     a[0], a[1], a[2], a[3]);
                mma16816(gc[m][0], gc[m][1], gc[m][2], gc[m][3],
                         a[0], a[1], a[2], a[3], b0, b1v);
            }
        }
        // store hgat (half2 pair = fragment cols) + staged es/ed partials
        int slot = w * 4 + (lane & 3);
        int p = (nb2 >> 1) + (lane & 3);
        #pragma unroll
        for (int m = 0; m < 2; m++)
            #pragma unroll
            for (int rr = 0; rr < 2; rr++) {
                int node = m * 16 + (lane >> 2) + rr * 8;
                int nid = nbase + node;
                int b = nid >> 12, n = nid & 4095;
                float h0 = gc[m][rr * 2 + 0], h1 = gc[m][rr * 2 + 1];
                ((__half2*)g_hgat4)[(n * 32 + p) * 8 + b] = __floats2half2_rn(h0, h1);
                sPES[node * 32 + slot] = h0 * sa[j0b] + h1 * sa[j0b + 1];
                sPED[node * 32 + slot] = h0 * sa[64 + j0b] + h1 * sa[64 + j0b + 1];
            }
        __syncthreads();
        if (tid < 32) {
            float es = 0.f, ed = 0.f;
            #pragma unroll 8
            for (int s = 0; s < 32; s++) {
                es += sPES[tid * 32 + s];
                ed += sPED[tid * 32 + s];
            }
            int nid = nbase + tid;
            int b = nid >> 12, n = nid & 4095;
            g_est[n * 8 + b] = es * LOG2E;
            g_edt[n * 8 + b] = ed * LOG2E;
        }
    } else {
        // output projection: h -> su, then out = h @ out_W + out_b
        #pragma unroll
        for (int m = 0; m < 2; m++)
            #pragma unroll
            for (int rr = 0; rr < 2; rr++) {
                int node = m * 16 + (lane >> 2) + rr * 8;
                su[node][j0b]     = hreg[m][rr][0];
                su[node][j0b + 1] = hreg[m][rr][1];
            }
        __syncthreads();
        if (tid < 96) {
            int ln = tid / 3, d = tid % 3;
            float acc3 = sob[d];
            #pragma unroll 8
            for (int k = 0; k < 64; k++) acc3 += su[ln][k] * sow[k * 3 + d];
            out[(nbase + ln) * 3 + d] = acc3;
        }
    }
}

// ---------------- launch ----------------
extern "C" void kernel_launch(void* const* d_in, const int* in_sizes, int n_in,
                              void* d_out, int out_size)
{
    const float* x       = (const float*)d_in[0];
    const int*   src     = (const int*)  d_in[1];
    const int*   dst     = (const int*)  d_in[2];
    const float* gat_W   = (const float*)d_in[3];
    const float* a_src   = (const float*)d_in[4];
    const float* a_dst   = (const float*)d_in[5];
    const float* gat_b   = (const float*)d_in[6];
    const float* gru1_W  = (const float*)d_in[7];
    const float* gru1_b  = (const float*)d_in[8];
    const float* gru2_W  = (const float*)d_in[9];
    const float* gru2_b  = (const float*)d_in[10];
    const float* out_W   = (const float*)d_in[11];
    const float* out_b   = (const float*)d_in[12];
    float* out = (float*)d_out;

    gat0_count_kernel<<<4096 + 272, 256>>>(x, gat_W, a_src, a_dst, dst);
    scan_kernel<<<1, 1024>>>();
    scatter_kernel<<<(EF + 255) / 256, 256>>>(src, dst);

    for (int t = 0; t < TT; t++) {
        gat_gather_kernel<<<NN / 4, 256>>>(gat_b);
        gru_kernel<<<BN / 32, 256>>>(x, gru1_W, gru1_b, gru2_W, gru2_b,
                                     gat_W, a_src, a_dst,
                                     out_W, out_b, out, t, (t == TT - 1) ? 1 : 0);
    }
}

// round 16
// speedup vs baseline: 1.7681x; 1.0778x over previous
#include <cuda_runtime.h>
#include <cuda_fp16.h>
#include <cuda_bf16.h>

#define BB 8
#define TT 4
#define NN 4096
#define EE 65536
#define EF (EE + NN)          // edges + self loops = 69632
#define BN (BB * NN)          // 32768
#define LOG2E 1.44269504f

// ---------------- device scratch ----------------
// hgat in fp16, layout [n][colpair p (32)][batch b (8)] as half2; uint4 = 4 batches
__device__ uint4   g_hgat4[NN * 32 * 2];   // 4 MB
__device__ float   g_est[NN * BB];         // es * log2e, transposed [n*8 + b]
__device__ float   g_edt[NN * BB];         // ed * log2e, transposed [n*8 + b]
__device__ uint4   g_s4[BN * 8];           // GAT output s, fp16 [b*NN+n][64]
__device__ uint4   g_W1h4[80 * 16];        // W1 fp16, rows permuted (s 0..63, x 64..66), 0-pad
__device__ uint4   g_W2h4[80 * 8];         // W2 fp16, permuted + 0-pad
__device__ uint4   g_gWh4[80 * 8];         // gat_W fp16, 0-pad (natural order: h 0..63, x 64..66)
__device__ int     g_cnt[NN];
__device__ int     g_cur[NN];
__device__ int     g_off[NN + 1];
__device__ int     g_srcs[EF];

__device__ __forceinline__ float ex2(float x) {
    float r; asm("ex2.approx.f32 %0, %1;" : "=f"(r) : "f"(x)); return r;
}
__device__ __forceinline__ unsigned sptr(const void* p) {
    return (unsigned)__cvta_generic_to_shared(p);
}
__device__ __forceinline__ void ldmA(unsigned addr, unsigned& a0, unsigned& a1,
                                     unsigned& a2, unsigned& a3) {
    asm volatile("ldmatrix.sync.aligned.m8n8.x4.shared.b16 {%0,%1,%2,%3}, [%4];"
        : "=r"(a0), "=r"(a1), "=r"(a2), "=r"(a3) : "r"(addr));
}
__device__ __forceinline__ void ldmBT(unsigned addr, unsigned& b0, unsigned& b1) {
    asm volatile("ldmatrix.sync.aligned.m8n8.x2.trans.shared.b16 {%0,%1}, [%2];"
        : "=r"(b0), "=r"(b1) : "r"(addr));
}
__device__ __forceinline__ void mma16816(float& c0, float& c1, float& c2, float& c3,
    unsigned a0, unsigned a1, unsigned a2, unsigned a3, unsigned b0, unsigned b1) {
    asm volatile("mma.sync.aligned.m16n8k16.row.col.f32.f16.f16.f32 "
        "{%0,%1,%2,%3}, {%4,%5,%6,%7}, {%8,%9}, {%0,%1,%2,%3};"
        : "+f"(c0), "+f"(c1), "+f"(c2), "+f"(c3)
        : "r"(a0), "r"(a1), "r"(a2), "r"(a3), "r"(b0), "r"(b1));
}

// ---------------- kernel 0: one-time weight fp16 conversion (permuted + padded) --
// W1h/W2h rows: 0..63 = s-block (orig rows 3..66), 64..66 = x-block (orig 0..2),
// 67..79 = zero. gat_W keeps natural order (h 0..63, x 64..66), rows 67..79 zero.
__global__ void wconv_kernel(const float* __restrict__ W1, const float* __restrict__ W2,
                             const float* __restrict__ gW)
{
    int r = blockIdx.x, c = threadIdx.x;        // 80 x 128
    __half* W1h = (__half*)g_W1h4;
    __half* W2h = (__half*)g_W2h4;
    __half* gWh = (__half*)g_gWh4;
    float v = 0.f;
    if (r < 64)      v = W1[(3 + r) * 128 + c];
    else if (r < 67) v = W1[(r - 64) * 128 + c];
    W1h[r * 128 + c] = __float2half(v);
    if (c < 64) {
        float v2 = 0.f, v3 = 0.f;
        if (r < 64)      v2 = W2[(3 + r) * 64 + c];
        else if (r < 67) v2 = W2[(r - 64) * 64 + c];
        if (r < 67)      v3 = gW[r * 64 + c];
        W2h[r * 64 + c] = __float2half(v2);
        gWh[r * 64 + c] = __float2half(v3);
    }
}

// ---------------- kernel 1: edge count + GAT step-0 node transform ----------------
__global__ __launch_bounds__(256) void gat0_count_kernel(
    const float* __restrict__ x, const float* __restrict__ gat_W,
    const float* __restrict__ a_src, const float* __restrict__ a_dst,
    const int* __restrict__ dst)
{
    if (blockIdx.x >= 4096) {
        int i = (blockIdx.x - 4096) * 256 + threadIdx.x;
        if (i < EF) {
            int d = (i < EE) ? dst[i] : (i - EE);
            atomicAdd(&g_cnt[d], 1);
        }
        return;
    }
    int w = threadIdx.x >> 5, lane = threadIdx.x & 31;
    int nid = blockIdx.x * 8 + w;
    int b = nid >> 12, n = nid & 4095;
    const float* xp = &x[((b * TT + 0) * NN + n) * 3];
    float x0 = __ldg(xp), x1 = __ldg(xp + 1), x2 = __ldg(xp + 2);
    int c0 = 2 * lane, c1 = 2 * lane + 1;
    float h0 = x0 * __ldg(&gat_W[64 * 64 + c0]) + x1 * __ldg(&gat_W[65 * 64 + c0])
             + x2 * __ldg(&gat_W[66 * 64 + c0]);
    float h1 = x0 * __ldg(&gat_W[64 * 64 + c1]) + x1 * __ldg(&gat_W[65 * 64 + c1])
             + x2 * __ldg(&gat_W[66 * 64 + c1]);
    ((__half2*)g_hgat4)[(n * 32 + lane) * 8 + b] = __floats2half2_rn(h0, h1);
    float es = h0 * __ldg(&a_src[c0]) + h1 * __ldg(&a_src[c1]);
    float ed = h0 * __ldg(&a_dst[c0]) + h1 * __ldg(&a_dst[c1]);
    #pragma unroll
    for (int o = 16; o > 0; o >>= 1) {
        es += __shfl_down_sync(0xFFFFFFFFu, es, o);
        ed += __shfl_down_sync(0xFFFFFFFFu, ed, o);
    }
    if (lane == 0) { g_est[n * 8 + b] = es * LOG2E; g_edt[n * 8 + b] = ed * LOG2E; }
}

// ---------------- kernel 2: prefix scan (+ re-zero counters for graph replay) ----
__global__ void scan_kernel() {
    __shared__ int tsum[1024];
    int tid = threadIdx.x;
    int base = tid * 4;
    int c0 = g_cnt[base + 0], c1 = g_cnt[base + 1];
    int c2 = g_cnt[base + 2], c3 = g_cnt[base + 3];
    int sum4 = c0 + c1 + c2 + c3;
    tsum[tid] = sum4;
    __syncthreads();
    for (int ofs = 1; ofs < 1024; ofs <<= 1) {
        int add = 0;
        if (tid >= ofs) add = tsum[tid - ofs];
        __syncthreads();
        tsum[tid] += add;
        __syncthreads();
    }
    int excl = tsum[tid] - sum4;
    g_off[base + 0] = excl;
    g_off[base + 1] = excl + c0;
    g_off[base + 2] = excl + c0 + c1;
    g_off[base + 3] = excl + c0 + c1 + c2;
    if (tid == 1023) g_off[NN] = tsum[1023];
    g_cnt[base + 0] = 0; g_cnt[base + 1] = 0; g_cnt[base + 2] = 0; g_cnt[base + 3] = 0;
    g_cur[base + 0] = 0; g_cur[base + 1] = 0; g_cur[base + 2] = 0; g_cur[base + 3] = 0;
}

// ---------------- kernel 3: CSR scatter ----------------
__global__ void scatter_kernel(const int* __restrict__ src, const int* __restrict__ dst) {
    int i = blockIdx.x * blockDim.x + threadIdx.x;
    if (i >= EF) return;
    int s, d;
    if (i < EE) { s = src[i]; d = dst[i]; }
    else        { s = i - EE; d = i - EE; }
    int pos = g_off[d] + atomicAdd(&g_cur[d], 1);
    g_srcs[pos] = s;
}

// ---------------- kernel 4: gather, 4 batches/warp, depth-2 pipeline -------------
__global__ __launch_bounds__(256) void gat_gather_kernel(const float* __restrict__ gat_b)
{
    int gw = blockIdx.x * 8 + (threadIdx.x >> 5);    // 0..8191
    int n = gw >> 1, bg = (gw & 1) * 4, bq = gw & 1;
    int lane = threadIdx.x & 31;

    float4 ed4 = *(const float4*)&g_edt[n * 8 + bg];
    float edv[4] = {ed4.x, ed4.y, ed4.z, ed4.w};
    float S[4], a0[4], a1[4];
    #pragma unroll
    for (int b = 0; b < 4; b++) { S[b] = 0.0f; a0[b] = 0.0f; a1[b] = 0.0f; }

    int e0 = g_off[n];
    int en1 = g_off[n + 1] - 1;
    int cnt = en1 - e0 + 1;
    int hofs = lane * 2 + bq;

    int sA = __ldg(&g_srcs[e0]);
    int s1 = __ldg(&g_srcs[min(e0 + 1, en1)]);
    int sC = __ldg(&g_srcs[min(e0 + 2, en1)]);
    int sD = __ldg(&g_srcs[min(e0 + 3, en1)]);
    float4 esv[2]; uint4 hv[2];
    esv[0] = *(const float4*)&g_est[sA * 8 + bg];
    hv[0]  = __ldg(&g_hgat4[sA * 64 + hofs]);
    esv[1] = *(const float4*)&g_est[s1 * 8 + bg];
    hv[1]  = __ldg(&g_hgat4[s1 * 64 + hofs]);

    #pragma unroll 2
    for (int i = 0; i < cnt; i++) {
        int cur = i & 1;
        float4 ces = esv[cur];
        uint4  ch  = hv[cur];
        esv[cur] = *(const float4*)&g_est[sC * 8 + bg];
        hv[cur]  = __ldg(&g_hgat4[sC * 64 + hofs]);
        sC = sD;
        sD = __ldg(&g_srcs[min(e0 + i + 4, en1)]);

        float esvv[4] = {ces.x, ces.y, ces.z, ces.w};
        unsigned hw[4] = {ch.x, ch.y, ch.z, ch.w};
        #pragma unroll
        for (int b = 0; b < 4; b++) {
            float ev = esvv[b] + edv[b];
            ev = fmaxf(ev, 0.2f * ev);
            float w = ex2(ev);
            float2 f = __half22float2(*(__half2*)&hw[b]);
            S[b] += w; a0[b] += w * f.x; a1[b] += w * f.y;
        }
    }
    float gb0 = __ldg(&gat_b[2 * lane]), gb1 = __ldg(&gat_b[2 * lane + 1]);
    #pragma unroll
    for (int b = 0; b < 4; b++) {
        float inv = 1.0f / S[b];
        ((__half2*)g_s4)[((bg + b) * NN + n) * 32 + lane] =
            __floats2half2_rn(a0[b] * inv + gb0, a1[b] * inv + gb1);
    }
}

// ---------------- kernel 5: GRU cell + fused GAT node transform (MMA fp16) -------
// 256 threads = 8 warps, 32 nodes/block. K padded 67->80 (zeros).
// A layout (s-first): s/rs at k 0..63, x at 64..66, 0-pad 67..79.
// phase1: [32x80] @ W1h[80x128]; phase2: [32x80] @ W2h[80x64];
// phase3 (t<3): hgat = [h, x(t+1)] @ gWh; es/ed staged smem reduce.
// last step: output projection instead of phase3.
__global__ __launch_bounds__(256) void gru_kernel(
    const float* __restrict__ x,
    const float* __restrict__ b1, const float* __restrict__ b2,
    const float* __restrict__ a_src, const float* __restrict__ a_dst,
    const float* __restrict__ oW, const float* __restrict__ ob,
    float* __restrict__ out, int t, int last)
{
    __shared__ __align__(16) __half sz[32][88];     // A1: s(0..63), x(64..66), 0 pad
    __shared__ __align__(16) __half szrs[32][88];   // A2: r*s,x ; phase3: h,x(t+1)
    __shared__ __align__(16) __half sW[80][136];    // W1h -> W2h -> gWh
    __shared__ float su[32][64];                    // u; phase3: es/ed partials; last: h
    __shared__ float sb1[128];
    __shared__ float sb2[64];
    __shared__ float sa[128];                       // a_src | a_dst
    __shared__ float sow[192];
    __shared__ float sob[4];
    float* sPES = &su[0][0];                        // [32 nodes][32 slots]
    float* sPED = &su[16][0];

    int tid = threadIdx.x;
    int lane = tid & 31;
    int w = tid >> 5;
    int nbase = blockIdx.x * 32;

    // W1h -> smem (pure uint4 copy, 80x16)
    for (int i = tid; i < 1280; i += 256) {
        int k = i >> 4, q = i & 15;
        *(uint4*)&sW[k][q * 8] = g_W1h4[i];
    }
    if (tid < 128) sb1[tid] = b1[tid];
    if (tid < 64)  sb2[tid] = b2[tid];
    if (last) {
        if (tid < 192) sow[tid] = oW[tid];
        if (tid < 3)   sob[tid] = ob[tid];
    }

    // s (fp16) -> sz[.][0..63] (pure uint4 copy, 32x8)
    for (int i = tid; i < 256; i += 256) {
        int ln = i >> 3, q = i & 7;
        *(uint4*)&sz[ln][q * 8] = g_s4[(nbase + ln) * 8 + q];
    }
    // zero pads k=67..79 in both A buffers
    for (int i = tid; i < 32 * 13; i += 256) {
        int ln = i / 13, k = 67 + (i % 13);
        sz[ln][k]   = __float2half(0.f);
        szrs[ln][k] = __float2half(0.f);
    }
    // x -> k 64..66 in both A buffers
    if (tid < 96) {
        int ln = tid / 3, f = tid % 3;
        int nid = nbase + ln;
        int b = nid >> 12, n = nid & 4095;
        __half hx = __float2half(x[((b * TT + t) * NN + n) * 3 + f]);
        sz[ln][64 + f]   = hx;
        szrs[ln][64 + f] = hx;
    }
    __syncthreads();

    // ---- phase 1 MMA: ru ----
    int nb = w * 16;
    float acc[2][2][4];
    #pragma unroll
    for (int m = 0; m < 2; m++)
        #pragma unroll
        for (int nt = 0; nt < 2; nt++) {
            int j0 = nb + nt * 8 + 2 * (lane & 3);
            acc[m][nt][0] = sb1[j0];     acc[m][nt][1] = sb1[j0 + 1];
            acc[m][nt][2] = sb1[j0];     acc[m][nt][3] = sb1[j0 + 1];
        }
    #pragma unroll
    for (int kb = 0; kb < 5; kb++) {
        unsigned a[2][4];
        #pragma unroll
        for (int m = 0; m < 2; m++)
            ldmA(sptr(&sz[m * 16 + (lane & 15)][kb * 16 + (lane >> 4) * 8]),
                 a[m][0], a[m][1], a[m][2], a[m][3]);
        #pragma unroll
        for (int nt = 0; nt < 2; nt++) {
            unsigned b0, b1v;
            ldmBT(sptr(&sW[kb * 16 + (lane & 15)][nb + nt * 8]), b0, b1v);
            #pragma unroll
            for (int m = 0; m < 2; m++)
                mma16816(acc[m][nt][0], acc[m][nt][1], acc[m][nt][2], acc[m][nt][3],
                         a[m][0], a[m][1], a[m][2], a[m][3], b0, b1v);
        }
    }

    // epilogue 1: sigmoid -> r*s (cols<64) / u (cols>=64)
    #pragma unroll
    for (int m = 0; m < 2; m++)
        #pragma unroll
        for (int nt = 0; nt < 2; nt++) {
            int j0 = nb + nt * 8 + 2 * (lane & 3);
            #pragma unroll
            for (int rr = 0; rr < 2; rr++) {
                int node = m * 16 + (lane >> 2) + rr * 8;
                float s0 = 1.f / (1.f + __expf(-acc[m][nt][rr * 2 + 0]));
                float s1 = 1.f / (1.f + __expf(-acc[m][nt][rr * 2 + 1]));
                if (j0 < 64) {
                    szrs[node][j0]     = __float2half(s0 * __half2float(sz[node][j0]));
                    szrs[node][j0 + 1] = __float2half(s1 * __half2float(sz[node][j0 + 1]));
                } else {
                    su[node][j0 - 64]     = s0;
                    su[node][j0 - 63]     = s1;
                }
            }
        }
    __syncthreads();   // all W1 reads + szrs/su writes complete

    // W2h -> smem (pure uint4 copy, 80x8)
    for (int i = tid; i < 640; i += 256) {
        int k = i >> 3, q = i & 7;
        *(uint4*)&sW[k][q * 8] = g_W2h4[i];
    }
    __syncthreads();

    // ---- phase 2 MMA: c ----
    int nb2 = w * 8;
    float a2c[2][4];
    {
        int j0 = nb2 + 2 * (lane & 3);
        #pragma unroll
        for (int m = 0; m < 2; m++) {
            a2c[m][0] = sb2[j0];     a2c[m][1] = sb2[j0 + 1];
            a2c[m][2] = sb2[j0];     a2c[m][3] = sb2[j0 + 1];
        }
    }
    #pragma unroll
    for (int kb = 0; kb < 5; kb++) {
        unsigned b0, b1v;
        ldmBT(sptr(&sW[kb * 16 + (lane & 15)][nb2]), b0, b1v);
        #pragma unroll
        for (int m = 0; m < 2; m++) {
            unsigned a[4];
            ldmA(sptr(&szrs[m * 16 + (lane & 15)][kb * 16 + (lane >> 4) * 8]),
                 a[0], a[1], a[2], a[3]);
            mma16816(a2c[m][0], a2c[m][1], a2c[m][2], a2c[m][3],
                     a[0], a[1], a[2], a[3], b0, b1v);
        }
    }

    // epilogue 2: c = tanh, h = u*s + (1-u)*c  (h kept in registers)
    int j0b = nb2 + 2 * (lane & 3);
    float hreg[2][2][2];
    #pragma unroll
    for (int m = 0; m < 2; m++)
        #pragma unroll
        for (int rr = 0; rr < 2; rr++) {
            int node = m * 16 + (lane >> 2) + rr * 8;
            float cc0 = tanhf(a2c[m][rr * 2 + 0]);
            float cc1 = tanhf(a2c[m][rr * 2 + 1]);
            float u0 = su[node][j0b], u1 = su[node][j0b + 1];
            float s0 = __half2float(sz[node][j0b]);
            float s1 = __half2float(sz[node][j0b + 1]);
            hreg[m][rr][0] = u0 * s0 + (1.f - u0) * cc0;
            hreg[m][rr][1] = u1 * s1 + (1.f - u1) * cc1;
        }
    __syncthreads();   // szrs/su/sW(W2) reads all complete

    if (!last) {
        // ---- phase 3: hgat = [h, x(t+1)] @ gat_W ----
        #pragma unroll
        for (int m = 0; m < 2; m++)
            #pragma unroll
            for (int rr = 0; rr < 2; rr++) {
                int node = m * 16 + (lane >> 2) + rr * 8;
                *(__half2*)&szrs[node][j0b] =
                    __floats2half2_rn(hreg[m][rr][0], hreg[m][rr][1]);
            }
        if (tid < 96) {
            int ln = tid / 3, f = tid % 3;
            int nid = nbase + ln;
            int b = nid >> 12, n = nid & 4095;
            szrs[ln][64 + f] = __float2half(x[((b * TT + t + 1) * NN + n) * 3 + f]);
        }
        // gWh -> smem (pure uint4 copy, 80x8; includes zero rows)
        for (int i = tid; i < 640; i += 256) {
            int k = i >> 3, q = i & 7;
            *(uint4*)&sW[k][q * 8] = g_gWh4[i];
        }
        if (tid < 128) sa[tid] = (tid < 64) ? a_src[tid] : a_dst[tid - 64];
        __syncthreads();

        float gc[2][4];
        #pragma unroll
        for (int m = 0; m < 2; m++)
            #pragma unroll
            for (int c = 0; c < 4; c++) gc[m][c] = 0.f;
        #pragma unroll
        for (int kb = 0; kb < 5; kb++) {
            unsigned b0, b1v;
            ldmBT(sptr(&sW[kb * 16 + (lane & 15)][nb2]), b0, b1v);
            #pragma unroll
            for (int m = 0; m < 2; m++) {
                unsigned a[4];
                ldmA(sptr(&szrs[m * 16 + (lane & 15)][kb * 16 + (lane >> 4) * 8]),
                     a[0], a[1], a[2], a[3]);
                mma16816(gc[m][0], gc[m][1], gc[m][2], gc[m][3],
                         a[0], a[1], a[2], a[3], b0, b1v);
            }
        }
        // store hgat (half2 pair = fragment cols) + staged es/ed partials
        int slot = w * 4 + (lane & 3);
        int p = (nb2 >> 1) + (lane & 3);
        #pragma unroll
        for (int m = 0; m < 2; m++)
            #pragma unroll
            for (int rr = 0; rr < 2; rr++) {
                int node = m * 16 + (lane >> 2) + rr * 8;
                int nid = nbase + node;
                int b = nid >> 12, n = nid & 4095;
                float h0 = gc[m][rr * 2 + 0], h1 = gc[m][rr * 2 + 1];
                ((__half2*)g_hgat4)[(n * 32 + p) * 8 + b] = __floats2half2_rn(h0, h1);
                sPES[node * 32 + slot] = h0 * sa[j0b] + h1 * sa[j0b + 1];
                sPED[node * 32 + slot] = h0 * sa[64 + j0b] + h1 * sa[64 + j0b + 1];
            }
        __syncthreads();
        if (tid < 32) {
            float es = 0.f, ed = 0.f;
            #pragma unroll 8
            for (int s = 0; s < 32; s++) {
                es += sPES[tid * 32 + s];
                ed += sPED[tid * 32 + s];
            }
            int nid = nbase + tid;
            int b = nid >> 12, n = nid & 4095;
            g_est[n * 8 + b] = es * LOG2E;
            g_edt[n * 8 + b] = ed * LOG2E;
        }
    } else {
        // output projection: h -> su, then out = h @ out_W + out_b
        #pragma unroll
        for (int m = 0; m < 2; m++)
            #pragma unroll
            for (int rr = 0; rr < 2; rr++) {
                int node = m * 16 + (lane >> 2) + rr * 8;
                su[node][j0b]     = hreg[m][rr][0];
                su[node][j0b + 1] = hreg[m][rr][1];
            }
        __syncthreads();
        if (tid < 96) {
            int ln = tid / 3, d = tid % 3;
            float acc3 = sob[d];
            #pragma unroll 8
            for (int k = 0; k < 64; k++) acc3 += su[ln][k] * sow[k * 3 + d];
            out[(nbase + ln) * 3 + d] = acc3;
        }
    }
}

// ---------------- launch ----------------
extern "C" void kernel_launch(void* const* d_in, const int* in_sizes, int n_in,
                              void* d_out, int out_size)
{
    const float* x       = (const float*)d_in[0];
    const int*   src     = (const int*)  d_in[1];
    const int*   dst     = (const int*)  d_in[2];
    const float* gat_W   = (const float*)d_in[3];
    const float* a_src   = (const float*)d_in[4];
    const float* a_dst   = (const float*)d_in[5];
    const float* gat_b   = (const float*)d_in[6];
    const float* gru1_W  = (const float*)d_in[7];
    const float* gru1_b  = (const float*)d_in[8];
    const float* gru2_W  = (const float*)d_in[9];
    const float* gru2_b  = (const float*)d_in[10];
    const float* out_W   = (const float*)d_in[11];
    const float* out_b   = (const float*)d_in[12];
    float* out = (float*)d_out;

    wconv_kernel<<<80, 128>>>(gru1_W, gru2_W, gat_W);
    gat0_count_kernel<<<4096 + 272, 256>>>(x, gat_W, a_src, a_dst, dst);
    scan_kernel<<<1, 1024>>>();
    scatter_kernel<<<(EF + 255) / 256, 256>>>(src, dst);

    for (int t = 0; t < TT; t++) {
        gat_gather_kernel<<<NN / 4, 256>>>(gat_b);
        gru_kernel<<<BN / 32, 256>>>(x, gru1_b, gru2_b, a_src, a_dst,
                                     out_W, out_b, out, t, (t == TT - 1) ? 1 : 0);
    }
}